// round 13
// baseline (speedup 1.0000x reference)
#include <cuda_runtime.h>
#include <math.h>

#define B_   64
#define C_   32
#define L_   1549
#define S_   512
#define HID_ 256
#define G4_  1024
#define D2_  512
#define NH_  8

typedef unsigned long long ull;

// ------------------------- f32x2 helpers (sm_103a packed fp32 FMA) -------------------------
__device__ __forceinline__ ull pack2(float lo, float hi) {
    ull r; asm("mov.b64 %0,{%1,%2};" : "=l"(r) : "f"(lo), "f"(hi)); return r;
}
__device__ __forceinline__ void unpack2(ull v, float& lo, float& hi) {
    asm("mov.b64 {%0,%1},%2;" : "=f"(lo), "=f"(hi) : "l"(v));
}
__device__ __forceinline__ ull fma2(ull a, ull b, ull c) {
    ull d; asm("fma.rn.f32x2 %0,%1,%2,%3;" : "=l"(d) : "l"(a), "l"(b), "l"(c)); return d;
}

// ------------------------- scratch (device globals) -------------------------
__device__ float g_h0 [(size_t)B_*S_*C_];
__device__ float g_xgf[(size_t)B_*S_*G4_];
__device__ float g_xgb[(size_t)B_*S_*G4_];
__device__ float g_out0[(size_t)B_*S_*D2_];
__device__ float g_out1[(size_t)B_*S_*D2_];
__device__ float g_q[(size_t)B_*S_*D2_];
__device__ float g_k[(size_t)B_*S_*D2_];
__device__ float g_v[(size_t)B_*S_*D2_];
__device__ float g_attn[(size_t)B_*NH_*S_*S_];
__device__ float g_ctx[(size_t)B_*S_*D2_];
__device__ float g_r[(size_t)B_*S_*D2_];

__device__ float g_wcT[C_*16*C_];
__device__ float g_wih0fT[C_*G4_],  g_wih0bT[C_*G4_];
__device__ float g_wih1fT[D2_*G4_], g_wih1bT[D2_*G4_];
__device__ float g_whh0fI[HID_*G4_], g_whh0bI[HID_*G4_];
__device__ float g_whh1fI[HID_*G4_], g_whh1bI[HID_*G4_];
__device__ float g_wqT[D2_*D2_], g_wkT[D2_*D2_], g_wvT[D2_*D2_];

__device__ __forceinline__ float sigm_(float x) { return 1.f/(1.f+__expf(-x)); }

__device__ __forceinline__ float blockReduceSum(float v) {
    __shared__ float sh[32];
    __syncthreads();
    int lane = threadIdx.x & 31, w = threadIdx.x >> 5;
    #pragma unroll
    for (int o = 16; o; o >>= 1) v += __shfl_down_sync(0xffffffffu, v, o);
    if (!lane) sh[w] = v;
    __syncthreads();
    if (w == 0) {
        int nw = blockDim.x >> 5;
        v = (lane < nw) ? sh[lane] : 0.f;
        #pragma unroll
        for (int o = 16; o; o >>= 1) v += __shfl_down_sync(0xffffffffu, v, o);
        if (!lane) sh[0] = v;
    }
    __syncthreads();
    return sh[0];
}

// ------------------------- weight reshapes -------------------------
__global__ void transpose_k(const float* __restrict__ in, float* __restrict__ out,
                            int N, int K) {
    int idx = blockIdx.x*blockDim.x + threadIdx.x;
    if (idx < N*K) {
        int n = idx % N, k = idx / N;
        out[idx] = in[(size_t)n*K + k];
    }
}
__global__ void convw_t_k(const float* __restrict__ in, float* __restrict__ out) {
    int idx = blockIdx.x*blockDim.x + threadIdx.x;
    if (idx < C_*16*C_) {
        int o = idx % C_, k = (idx / C_) % 16, i = idx / (C_*16);
        out[idx] = in[((size_t)o*C_ + i)*16 + k];
    }
}
// W_hh (1024,256) -> interleaved [k][4*j+g] = W[g*256+j][k]
__global__ void whh_int_k(const float* __restrict__ in, float* __restrict__ out) {
    int idx = blockIdx.x*blockDim.x + threadIdx.x;
    if (idx < HID_*G4_) {
        int col = idx % G4_, k = idx / G4_;
        int j = col >> 2, g = col & 3;
        out[idx] = in[((size_t)g*HID_ + j)*HID_ + k];
    }
}

// ------------------------- conv1d + bn + relu + maxpool3 -------------------------
__global__ void conv_bn_pool_k(const float* __restrict__ x, const float* __restrict__ wcT,
                               const float* __restrict__ cb, const float* __restrict__ gma,
                               const float* __restrict__ bta, const float* __restrict__ mean,
                               const float* __restrict__ var, float* __restrict__ h0) {
    int c  = threadIdx.x & 31;
    int si = threadIdx.x >> 5;
    int s  = (blockIdx.x << 2) + si;
    int b  = blockIdx.y;
    float scale = gma[c] * rsqrtf(var[c] + 1e-5f);
    float shift = bta[c] - mean[c]*scale;
    float a0 = cb[c], a1 = cb[c], a2 = cb[c];
    const float* xb = x + (size_t)b*C_*L_;
    int l0 = 3*s - 1;
    for (int ci = 0; ci < C_; ++ci) {
        const float* xc = xb + (size_t)ci*L_;
        float xv[18];
        #pragma unroll
        for (int qd = 0; qd < 18; ++qd) {
            int idx = l0 + qd;
            xv[qd] = (idx >= 0 && idx < L_) ? xc[idx] : 0.f;
        }
        const float* w = wcT + (size_t)ci*16*C_ + c;
        #pragma unroll
        for (int kk = 0; kk < 16; ++kk) {
            float wv = w[(size_t)kk*C_];
            a0 = fmaf(xv[kk+0], wv, a0);
            a1 = fmaf(xv[kk+1], wv, a1);
            a2 = fmaf(xv[kk+2], wv, a2);
        }
    }
    a0 = fmaxf(fmaf(a0, scale, shift), 0.f);
    a1 = fmaxf(fmaf(a1, scale, shift), 0.f);
    a2 = fmaxf(fmaf(a2, scale, shift), 0.f);
    h0[((size_t)b*S_ + s)*C_ + c] = fmaxf(a0, fmaxf(a1, a2));
}

// ------------------------- SGEMM (f32x2, double-buffered): C = A@Bm + bias -------------------------
// 128x128 tile, BK=8, 256 threads, 8x8 microtile (4 f32x2 pairs per row).
__global__ void __launch_bounds__(256) sgemm_bias_k(
    const float* __restrict__ A, const float* __restrict__ Bm,
    const float* __restrict__ bias, float* __restrict__ C,
    int M, int N, int K) {
    __shared__ __align__(16) float As[2][8][128];
    __shared__ __align__(16) float Bs[2][8][128];
    int tid = threadIdx.x;
    int m0 = blockIdx.y << 7;
    int n0 = blockIdx.x << 7;
    int arow = tid >> 1, acol = (tid & 1) << 2;
    int brow = tid >> 5, bcol = (tid & 31) << 2;
    int tr = tid >> 4, tc = tid & 15;
    ull acc[8][4];
    #pragma unroll
    for (int i = 0; i < 8; ++i)
        #pragma unroll
        for (int p = 0; p < 4; ++p) acc[i][p] = 0ull;

    const float* Ap = A + (size_t)(m0 + arow)*K + acol;
    const float* Bp = Bm + (size_t)brow*N + n0 + bcol;

    {   // prologue: tile 0
        float4 av = *(const float4*)Ap;
        float4 bv = *(const float4*)Bp;
        As[0][acol+0][arow] = av.x; As[0][acol+1][arow] = av.y;
        As[0][acol+2][arow] = av.z; As[0][acol+3][arow] = av.w;
        *(float4*)&Bs[0][brow][bcol] = bv;
    }
    __syncthreads();

    int buf = 0;
    for (int k0 = 0; k0 < K; k0 += 8) {
        float4 av2, bv2;
        bool more = (k0 + 8) < K;
        if (more) {
            av2 = *(const float4*)(Ap + k0 + 8);
            bv2 = *(const float4*)(Bp + (size_t)(k0 + 8)*N);
        }
        #pragma unroll
        for (int kk = 0; kk < 8; ++kk) {
            float a8[8];
            *(float4*)(a8)   = *(const float4*)&As[buf][kk][tr*8];
            *(float4*)(a8+4) = *(const float4*)&As[buf][kk][tr*8+4];
            const ull* bp2 = (const ull*)&Bs[buf][kk][tc*8];
            ull b4[4];
            b4[0] = bp2[0]; b4[1] = bp2[1]; b4[2] = bp2[2]; b4[3] = bp2[3];
            #pragma unroll
            for (int i = 0; i < 8; ++i) {
                ull a2 = pack2(a8[i], a8[i]);
                #pragma unroll
                for (int p = 0; p < 4; ++p)
                    acc[i][p] = fma2(a2, b4[p], acc[i][p]);
            }
        }
        if (more) {
            As[buf^1][acol+0][arow] = av2.x; As[buf^1][acol+1][arow] = av2.y;
            As[buf^1][acol+2][arow] = av2.z; As[buf^1][acol+3][arow] = av2.w;
            *(float4*)&Bs[buf^1][brow][bcol] = bv2;
        }
        __syncthreads();
        buf ^= 1;
    }

    float bb[8];
    #pragma unroll
    for (int j = 0; j < 8; ++j) bb[j] = bias[n0 + tc*8 + j];
    #pragma unroll
    for (int i = 0; i < 8; ++i) {
        float* Cp = C + (size_t)(m0 + tr*8 + i)*N + n0 + tc*8;
        #pragma unroll
        for (int p = 0; p < 4; ++p) {
            float lo, hi; unpack2(acc[i][p], lo, hi);
            Cp[2*p]   = lo + bb[2*p];
            Cp[2*p+1] = hi + bb[2*p+1];
        }
    }
}

// ------------------------- BiLSTM recurrence (4 batches/CTA, f32x2) -------------------------
// grid (B/4, 2 dirs), block 256. whhI interleaved: [k][4*j+{i,f,g,o}].
__global__ void __launch_bounds__(256) lstm_k(
    const float* __restrict__ xgf, const float* __restrict__ xgb,
    const float* __restrict__ whhfI, const float* __restrict__ whhbI,
    float* __restrict__ out) {
    int tid = threadIdx.x;
    int dir = blockIdx.y;
    int b0  = blockIdx.x << 2;
    const float* xg = dir ? xgb : xgf;
    const float* w  = dir ? whhbI : whhfI;
    __shared__ __align__(16) ull hp01[HID_];
    __shared__ __align__(16) ull hp23[HID_];
    hp01[tid] = 0ull; hp23[tid] = 0ull;
    float c0 = 0.f, c1 = 0.f, c2 = 0.f, c3 = 0.f;
    const float* wp = w + 4*tid;
    for (int step = 0; step < S_; ++step) {
        __syncthreads();
        ull acc01[4], acc23[4];
        #pragma unroll
        for (int g = 0; g < 4; ++g) { acc01[g] = 0ull; acc23[g] = 0ull; }
        #pragma unroll 8
        for (int k = 0; k < HID_; ++k) {
            float4 w4 = *(const float4*)(wp + (size_t)k*G4_);
            ull h01 = hp01[k], h23 = hp23[k];
            ull wx = pack2(w4.x, w4.x), wy = pack2(w4.y, w4.y);
            ull wz = pack2(w4.z, w4.z), ww = pack2(w4.w, w4.w);
            acc01[0] = fma2(h01, wx, acc01[0]); acc23[0] = fma2(h23, wx, acc23[0]);
            acc01[1] = fma2(h01, wy, acc01[1]); acc23[1] = fma2(h23, wy, acc23[1]);
            acc01[2] = fma2(h01, wz, acc01[2]); acc23[2] = fma2(h23, wz, acc23[2]);
            acc01[3] = fma2(h01, ww, acc01[3]); acc23[3] = fma2(h23, ww, acc23[3]);
        }
        int t = dir ? (S_-1-step) : step;
        float a0[4], a1[4], a2[4], a3[4];
        #pragma unroll
        for (int g = 0; g < 4; ++g) {
            float lo, hi;
            unpack2(acc01[g], lo, hi); a0[g] = lo; a1[g] = hi;
            unpack2(acc23[g], lo, hi); a2[g] = lo; a3[g] = hi;
        }
        const float* x0 = xg + ((size_t)(b0+0)*S_ + t)*G4_;
        const float* x1 = xg + ((size_t)(b0+1)*S_ + t)*G4_;
        const float* x2 = xg + ((size_t)(b0+2)*S_ + t)*G4_;
        const float* x3 = xg + ((size_t)(b0+3)*S_ + t)*G4_;
        #pragma unroll
        for (int g = 0; g < 4; ++g) {
            a0[g] += x0[g*HID_ + tid]; a1[g] += x1[g*HID_ + tid];
            a2[g] += x2[g*HID_ + tid]; a3[g] += x3[g*HID_ + tid];
        }
        c0 = sigm_(a0[1])*c0 + sigm_(a0[0])*tanhf(a0[2]); float h0 = sigm_(a0[3])*tanhf(c0);
        c1 = sigm_(a1[1])*c1 + sigm_(a1[0])*tanhf(a1[2]); float h1 = sigm_(a1[3])*tanhf(c1);
        c2 = sigm_(a2[1])*c2 + sigm_(a2[0])*tanhf(a2[2]); float h2 = sigm_(a2[3])*tanhf(c2);
        c3 = sigm_(a3[1])*c3 + sigm_(a3[0])*tanhf(a3[2]); float h3 = sigm_(a3[3])*tanhf(c3);
        __syncthreads();
        hp01[tid] = pack2(h0, h1);
        hp23[tid] = pack2(h2, h3);
        size_t od = (size_t)dir*HID_ + tid;
        out[((size_t)(b0+0)*S_ + t)*D2_ + od] = h0;
        out[((size_t)(b0+1)*S_ + t)*D2_ + od] = h1;
        out[((size_t)(b0+2)*S_ + t)*D2_ + od] = h2;
        out[((size_t)(b0+3)*S_ + t)*D2_ + od] = h3;
    }
}

// ------------------------- attention scores (f32x2) -------------------------
// grid (t-tiles=8, s-tiles=8, B*NH), block 256. attn[b][h][s][t] = q.k/8
__global__ void __launch_bounds__(256) attn_scores_k(
    const float* __restrict__ q, const float* __restrict__ k,
    float* __restrict__ attn) {
    __shared__ __align__(16) float Qs[64][66];
    __shared__ __align__(16) float KsT[64][66];   // [d][t]
    int tid = threadIdx.x;
    int bh = blockIdx.z; int b = bh >> 3, h = bh & 7;
    int s0 = blockIdx.y << 6, t0 = blockIdx.x << 6;
    const float* qb = q + ((size_t)b*S_ + s0)*D2_ + h*64;
    const float* kb = k + ((size_t)b*S_ + t0)*D2_ + h*64;
    for (int i = tid; i < 64*64; i += 256) {
        int r = i >> 6, cc = i & 63;
        Qs[r][cc]  = qb[(size_t)r*D2_ + cc];
        KsT[cc][r] = kb[(size_t)r*D2_ + cc];
    }
    __syncthreads();
    int tr = tid >> 4, tc = tid & 15;
    ull acc[4][2];
    #pragma unroll
    for (int i = 0; i < 4; ++i) { acc[i][0] = 0ull; acc[i][1] = 0ull; }
    #pragma unroll 4
    for (int d = 0; d < 64; ++d) {
        const ull* kp = (const ull*)&KsT[d][tc*4];
        ull k2a = kp[0], k2b = kp[1];
        #pragma unroll
        for (int i = 0; i < 4; ++i) {
            float qv = Qs[tr*4+i][d];
            ull q2 = pack2(qv, qv);
            acc[i][0] = fma2(q2, k2a, acc[i][0]);
            acc[i][1] = fma2(q2, k2b, acc[i][1]);
        }
    }
    float* ap = attn + (((size_t)bh*S_ + s0 + tr*4)*S_ + t0 + tc*4);
    #pragma unroll
    for (int i = 0; i < 4; ++i) {
        float lo, hi;
        unpack2(acc[i][0], lo, hi);
        ap[(size_t)i*S_ + 0] = lo*0.125f; ap[(size_t)i*S_ + 1] = hi*0.125f;
        unpack2(acc[i][1], lo, hi);
        ap[(size_t)i*S_ + 2] = lo*0.125f; ap[(size_t)i*S_ + 3] = hi*0.125f;
    }
}

// ------------------------- log-softmax over heads (axis=1) -------------------------
__global__ void logsoftmax_h_k(float* __restrict__ attn) {
    size_t idx = (size_t)blockIdx.x*blockDim.x + threadIdx.x;
    size_t total = (size_t)B_*S_*S_;
    if (idx >= total) return;
    int t = idx & (S_-1);
    int s = (idx >> 9) & (S_-1);
    int b = idx >> 18;
    float* p = attn + (((size_t)b*NH_)*S_ + s)*S_ + t;
    const size_t hs = (size_t)S_*S_;
    float v[NH_];
    float m = -1e30f;
    #pragma unroll
    for (int h = 0; h < NH_; ++h) { v[h] = p[h*hs]; m = fmaxf(m, v[h]); }
    float sum = 0.f;
    #pragma unroll
    for (int h = 0; h < NH_; ++h) sum += __expf(v[h] - m);
    float lse = __logf(sum) + m;
    #pragma unroll
    for (int h = 0; h < NH_; ++h) p[h*hs] = v[h] - lse;
}

// ------------------------- ctx = la @ v (f32x2) -------------------------
// grid (s-tiles=8, B*NH), block 256. ctx stored [b][s][h*64+d]
__global__ void __launch_bounds__(256) attn_ctx_k(
    const float* __restrict__ la, const float* __restrict__ v,
    float* __restrict__ ctx) {
    __shared__ __align__(16) float Ls[64][66];
    __shared__ __align__(16) float Vs[64][66];
    int tid = threadIdx.x;
    int bh = blockIdx.y; int b = bh >> 3, h = bh & 7;
    int s0 = blockIdx.x << 6;
    int tr = tid >> 4, tc = tid & 15;
    ull acc[4][2];
    #pragma unroll
    for (int i = 0; i < 4; ++i) { acc[i][0] = 0ull; acc[i][1] = 0ull; }
    for (int t0 = 0; t0 < S_; t0 += 64) {
        for (int i = tid; i < 64*64; i += 256) {
            int r = i >> 6, cc = i & 63;
            Ls[r][cc] = la[(((size_t)bh*S_) + s0 + r)*S_ + t0 + cc];
            Vs[r][cc] = v[((size_t)b*S_ + t0 + r)*D2_ + h*64 + cc];
        }
        __syncthreads();
        #pragma unroll 4
        for (int kk = 0; kk < 64; ++kk) {
            const ull* vp = (const ull*)&Vs[kk][tc*4];
            ull v2a = vp[0], v2b = vp[1];
            #pragma unroll
            for (int i = 0; i < 4; ++i) {
                float av = Ls[tr*4+i][kk];
                ull a2 = pack2(av, av);
                acc[i][0] = fma2(a2, v2a, acc[i][0]);
                acc[i][1] = fma2(a2, v2b, acc[i][1]);
            }
        }
        __syncthreads();
    }
    #pragma unroll
    for (int i = 0; i < 4; ++i) {
        float* cp = ctx + ((size_t)b*S_ + s0 + tr*4 + i)*D2_ + h*64 + tc*4;
        float lo, hi;
        unpack2(acc[i][0], lo, hi); cp[0] = lo; cp[1] = hi;
        unpack2(acc[i][1], lo, hi); cp[2] = lo; cp[3] = hi;
    }
}

// ------------------------- residual + layernorm -------------------------
__global__ void __launch_bounds__(256) res_ln_k(
    const float* __restrict__ out1, const float* __restrict__ ctx,
    const float* __restrict__ lng, const float* __restrict__ lnb,
    float* __restrict__ r) {
    size_t row = blockIdx.x;
    int tid = threadIdx.x;
    const float* o = out1 + row*D2_;
    const float* c = ctx  + row*D2_;
    float v0 = o[tid] + c[tid];
    float v1 = o[tid+256] + c[tid+256];
    float mu = blockReduceSum(v0 + v1) * (1.f/D2_);
    float d0 = v0 - mu, d1 = v1 - mu;
    float var = blockReduceSum(d0*d0 + d1*d1) * (1.f/D2_);
    float rs = rsqrtf(var + 1e-5f);
    r[row*D2_ + tid]       = d0*rs*lng[tid]     + lnb[tid];
    r[row*D2_ + tid + 256] = d1*rs*lng[tid+256] + lnb[tid+256];
}

// ------------------------- mean pool + fc -------------------------
__global__ void __launch_bounds__(256) pool_fc_k(
    const float* __restrict__ r, const float* __restrict__ fcw,
    const float* __restrict__ fcb, float* __restrict__ out) {
    int b = blockIdx.x, tid = threadIdx.x;
    const float* rb = r + (size_t)b*S_*D2_;
    float acc = 0.f;
    for (int i = tid; i < S_*D2_; i += 256)
        acc = fmaf(rb[i], fcw[i & (D2_-1)], acc);
    float total = blockReduceSum(acc);
    if (tid == 0) out[b] = total * (1.f/S_) + fcb[0];
}

// ------------------------- launch -------------------------
static float* devptr(const void* sym) {
    void* p = nullptr;
    cudaGetSymbolAddress(&p, sym);
    return (float*)p;
}

extern "C" void kernel_launch(void* const* d_in, const int* in_sizes, int n_in,
                              void* d_out, int out_size) {
    const float* x       = (const float*)d_in[0];
    const float* conv_w  = (const float*)d_in[1];
    const float* conv_b  = (const float*)d_in[2];
    const float* bn_g    = (const float*)d_in[3];
    const float* bn_b    = (const float*)d_in[4];
    const float* bn_m    = (const float*)d_in[5];
    const float* bn_v    = (const float*)d_in[6];
    const float* W_ih0f  = (const float*)d_in[7];
    const float* W_hh0f  = (const float*)d_in[8];
    const float* b0f     = (const float*)d_in[9];
    const float* W_ih0b  = (const float*)d_in[10];
    const float* W_hh0b  = (const float*)d_in[11];
    const float* b0b     = (const float*)d_in[12];
    const float* W_ih1f  = (const float*)d_in[13];
    const float* W_hh1f  = (const float*)d_in[14];
    const float* b1f     = (const float*)d_in[15];
    const float* W_ih1b  = (const float*)d_in[16];
    const float* W_hh1b  = (const float*)d_in[17];
    const float* b1b     = (const float*)d_in[18];
    const float* Wq      = (const float*)d_in[19];
    const float* bq      = (const float*)d_in[20];
    const float* Wk      = (const float*)d_in[21];
    const float* bk      = (const float*)d_in[22];
    const float* Wv      = (const float*)d_in[23];
    const float* bv      = (const float*)d_in[24];
    const float* ln_g    = (const float*)d_in[25];
    const float* ln_b    = (const float*)d_in[26];
    const float* fc_w    = (const float*)d_in[27];
    const float* fc_b    = (const float*)d_in[28];
    float* out = (float*)d_out;

    float* p_h0   = devptr(g_h0);
    float* p_xgf  = devptr(g_xgf);
    float* p_xgb  = devptr(g_xgb);
    float* p_out0 = devptr(g_out0);
    float* p_out1 = devptr(g_out1);
    float* p_q    = devptr(g_q);
    float* p_k    = devptr(g_k);
    float* p_v    = devptr(g_v);
    float* p_attn = devptr(g_attn);
    float* p_ctx  = devptr(g_ctx);
    float* p_r    = devptr(g_r);
    float* p_wcT  = devptr(g_wcT);
    float* p_ih0f = devptr(g_wih0fT);
    float* p_ih0b = devptr(g_wih0bT);
    float* p_ih1f = devptr(g_wih1fT);
    float* p_ih1b = devptr(g_wih1bT);
    float* p_hh0f = devptr(g_whh0fI);
    float* p_hh0b = devptr(g_whh0bI);
    float* p_hh1f = devptr(g_whh1fI);
    float* p_hh1b = devptr(g_whh1bI);
    float* p_wqT  = devptr(g_wqT);
    float* p_wkT  = devptr(g_wkT);
    float* p_wvT  = devptr(g_wvT);

    const int M = B_*S_;  // 32768

    // weight reshapes
    convw_t_k<<<(C_*16*C_+255)/256, 256>>>(conv_w, p_wcT);
    transpose_k<<<(G4_*C_+255)/256, 256>>>(W_ih0f, p_ih0f, G4_, C_);
    transpose_k<<<(G4_*C_+255)/256, 256>>>(W_ih0b, p_ih0b, G4_, C_);
    transpose_k<<<(G4_*D2_+255)/256, 256>>>(W_ih1f, p_ih1f, G4_, D2_);
    transpose_k<<<(G4_*D2_+255)/256, 256>>>(W_ih1b, p_ih1b, G4_, D2_);
    whh_int_k<<<(HID_*G4_+255)/256, 256>>>(W_hh0f, p_hh0f);
    whh_int_k<<<(HID_*G4_+255)/256, 256>>>(W_hh0b, p_hh0b);
    whh_int_k<<<(HID_*G4_+255)/256, 256>>>(W_hh1f, p_hh1f);
    whh_int_k<<<(HID_*G4_+255)/256, 256>>>(W_hh1b, p_hh1b);
    transpose_k<<<(D2_*D2_+255)/256, 256>>>(Wq, p_wqT, D2_, D2_);
    transpose_k<<<(D2_*D2_+255)/256, 256>>>(Wk, p_wkT, D2_, D2_);
    transpose_k<<<(D2_*D2_+255)/256, 256>>>(Wv, p_wvT, D2_, D2_);

    // conv front-end
    conv_bn_pool_k<<<dim3(S_/4, B_), 128>>>(x, p_wcT, conv_b, bn_g, bn_b, bn_m, bn_v, p_h0);

    // layer 0 gates + recurrence
    sgemm_bias_k<<<dim3(G4_/128, M/128), 256>>>(p_h0, p_ih0f, b0f, p_xgf, M, G4_, C_);
    sgemm_bias_k<<<dim3(G4_/128, M/128), 256>>>(p_h0, p_ih0b, b0b, p_xgb, M, G4_, C_);
    lstm_k<<<dim3(B_/4, 2), 256>>>(p_xgf, p_xgb, p_hh0f, p_hh0b, p_out0);

    // layer 1 gates + recurrence
    sgemm_bias_k<<<dim3(G4_/128, M/128), 256>>>(p_out0, p_ih1f, b1f, p_xgf, M, G4_, D2_);
    sgemm_bias_k<<<dim3(G4_/128, M/128), 256>>>(p_out0, p_ih1b, b1b, p_xgb, M, G4_, D2_);
    lstm_k<<<dim3(B_/4, 2), 256>>>(p_xgf, p_xgb, p_hh1f, p_hh1b, p_out1);

    // QKV
    sgemm_bias_k<<<dim3(D2_/128, M/128), 256>>>(p_out1, p_wqT, bq, p_q, M, D2_, D2_);
    sgemm_bias_k<<<dim3(D2_/128, M/128), 256>>>(p_out1, p_wkT, bk, p_k, M, D2_, D2_);
    sgemm_bias_k<<<dim3(D2_/128, M/128), 256>>>(p_out1, p_wvT, bv, p_v, M, D2_, D2_);

    // attention
    attn_scores_k<<<dim3(S_/64, S_/64, B_*NH_), 256>>>(p_q, p_k, p_attn);
    logsoftmax_h_k<<<(int)(((size_t)B_*S_*S_ + 255)/256), 256>>>(p_attn);
    attn_ctx_k<<<dim3(S_/64, B_*NH_), 256>>>(p_attn, p_v, p_ctx);

    // residual + LN + pool + fc
    res_ln_k<<<M, 256>>>(p_out1, p_ctx, ln_g, ln_b, p_r);
    pool_fc_k<<<B_, 256>>>(p_r, fc_w, fc_b, out);

    (void)in_sizes; (void)n_in; (void)out_size;
}

// round 14
// speedup vs baseline: 1.2778x; 1.2778x over previous
#include <cuda_runtime.h>
#include <math.h>

#define B_   64
#define C_   32
#define L_   1549
#define S_   512
#define HID_ 256
#define G4_  1024
#define D2_  512
#define NH_  8

// ------------------------- scratch (device globals) -------------------------
__device__ float g_h0 [(size_t)B_*S_*C_];
__device__ float g_xgf[(size_t)B_*S_*G4_];
__device__ float g_xgb[(size_t)B_*S_*G4_];
__device__ float g_out0[(size_t)B_*S_*D2_];
__device__ float g_out1[(size_t)B_*S_*D2_];
__device__ float g_q[(size_t)B_*S_*D2_];
__device__ float g_k[(size_t)B_*S_*D2_];
__device__ float g_v[(size_t)B_*S_*D2_];
__device__ float g_attn[(size_t)B_*NH_*S_*S_];
__device__ float g_ctx[(size_t)B_*S_*D2_];
__device__ float g_r[(size_t)B_*S_*D2_];

__device__ float g_wcT[C_*16*C_];
__device__ float g_whh0fI[HID_*G4_], g_whh0bI[HID_*G4_];
__device__ float g_whh1fI[HID_*G4_], g_whh1bI[HID_*G4_];

__device__ __forceinline__ float sigm_(float x) { return 1.f/(1.f+__expf(-x)); }

__device__ __forceinline__ float tf32r(float x) {
    unsigned u;
    asm("cvt.rna.tf32.f32 %0,%1;" : "=r"(u) : "f"(x));
    return __uint_as_float(u);
}

__device__ __forceinline__ void mma8(float* c, const unsigned* a, const unsigned* b) {
    asm volatile("mma.sync.aligned.m16n8k8.row.col.f32.tf32.tf32.f32 "
        "{%0,%1,%2,%3},{%4,%5,%6,%7},{%8,%9},{%0,%1,%2,%3};"
        : "+f"(c[0]), "+f"(c[1]), "+f"(c[2]), "+f"(c[3])
        : "r"(a[0]), "r"(a[1]), "r"(a[2]), "r"(a[3]), "r"(b[0]), "r"(b[1]));
}

__device__ __forceinline__ float blockReduceSum(float v) {
    __shared__ float sh[32];
    __syncthreads();
    int lane = threadIdx.x & 31, w = threadIdx.x >> 5;
    #pragma unroll
    for (int o = 16; o; o >>= 1) v += __shfl_down_sync(0xffffffffu, v, o);
    if (!lane) sh[w] = v;
    __syncthreads();
    if (w == 0) {
        int nw = blockDim.x >> 5;
        v = (lane < nw) ? sh[lane] : 0.f;
        #pragma unroll
        for (int o = 16; o; o >>= 1) v += __shfl_down_sync(0xffffffffu, v, o);
        if (!lane) sh[0] = v;
    }
    __syncthreads();
    return sh[0];
}

// ------------------------- fused weight reshapes (one launch) -------------------------
// y=0: conv_w (O,I,K16) -> wcT[i][k][o]; y=1..4: W_hh -> interleaved [k][4j+g]
__global__ void reshape_all_k(const float* __restrict__ cw,
                              const float* __restrict__ h0f, const float* __restrict__ h0b,
                              const float* __restrict__ h1f, const float* __restrict__ h1b,
                              float* __restrict__ wcT,
                              float* __restrict__ w0f, float* __restrict__ w0b,
                              float* __restrict__ w1f, float* __restrict__ w1b) {
    int idx = blockIdx.x*blockDim.x + threadIdx.x;
    int which = blockIdx.y;
    if (which == 0) {
        if (idx < C_*16*C_) {
            int o = idx % C_, kk = (idx / C_) % 16, i = idx / (C_*16);
            wcT[idx] = cw[((size_t)o*C_ + i)*16 + kk];
        }
    } else {
        const float* in  = (which==1)?h0f:(which==2)?h0b:(which==3)?h1f:h1b;
        float*       out = (which==1)?w0f:(which==2)?w0b:(which==3)?w1f:w1b;
        if (idx < HID_*G4_) {
            int col = idx % G4_, kk = idx / G4_;
            int j = col >> 2, g = col & 3;
            out[idx] = in[((size_t)g*HID_ + j)*HID_ + kk];
        }
    }
}

// ------------------------- conv1d + bn + relu + maxpool3 -------------------------
__global__ void conv_bn_pool_k(const float* __restrict__ x, const float* __restrict__ wcT,
                               const float* __restrict__ cb, const float* __restrict__ gma,
                               const float* __restrict__ bta, const float* __restrict__ mean,
                               const float* __restrict__ var, float* __restrict__ h0) {
    int c  = threadIdx.x & 31;
    int si = threadIdx.x >> 5;
    int s  = (blockIdx.x << 2) + si;
    int b  = blockIdx.y;
    float scale = gma[c] * rsqrtf(var[c] + 1e-5f);
    float shift = bta[c] - mean[c]*scale;
    float a0 = cb[c], a1 = cb[c], a2 = cb[c];
    const float* xb = x + (size_t)b*C_*L_;
    int l0 = 3*s - 1;
    for (int ci = 0; ci < C_; ++ci) {
        const float* xc = xb + (size_t)ci*L_;
        float xv[18];
        #pragma unroll
        for (int qd = 0; qd < 18; ++qd) {
            int idx = l0 + qd;
            xv[qd] = (idx >= 0 && idx < L_) ? xc[idx] : 0.f;
        }
        const float* w = wcT + (size_t)ci*16*C_ + c;
        #pragma unroll
        for (int kk = 0; kk < 16; ++kk) {
            float wv = w[(size_t)kk*C_];
            a0 = fmaf(xv[kk+0], wv, a0);
            a1 = fmaf(xv[kk+1], wv, a1);
            a2 = fmaf(xv[kk+2], wv, a2);
        }
    }
    a0 = fmaxf(fmaf(a0, scale, shift), 0.f);
    a1 = fmaxf(fmaf(a1, scale, shift), 0.f);
    a2 = fmaxf(fmaf(a2, scale, shift), 0.f);
    h0[((size_t)b*S_ + s)*C_ + c] = fmaxf(a0, fmaxf(a1, a2));
}

// ------------------------- TF32 tensor-core GEMM: C = A(MxK) @ W(N,K)^T + bias ----------
// block 256 thr = 8 warps (2x4), tile 128x128, BK=32, warp tile 64x32, mma m16n8k8.
// M,N multiples of 128; K multiple of 32.
__global__ void __launch_bounds__(256) gemm_tf32_k(
    const float* __restrict__ A, const float* __restrict__ W,
    const float* __restrict__ bias, float* __restrict__ C,
    int M, int N, int K) {
    __shared__ float As[128][36];
    __shared__ float Bs[128][36];
    int tid = threadIdx.x;
    int lane = tid & 31, wid = tid >> 5;
    int warp_m = wid & 1, warp_n = wid >> 1;
    int m0 = blockIdx.y << 7, n0 = blockIdx.x << 7;

    float acc[4][4][4];
    #pragma unroll
    for (int i = 0; i < 4; ++i)
        #pragma unroll
        for (int j = 0; j < 4; ++j)
            #pragma unroll
            for (int p = 0; p < 4; ++p) acc[i][j][p] = 0.f;

    for (int k0 = 0; k0 < K; k0 += 32) {
        #pragma unroll
        for (int i = 0; i < 4; ++i) {
            int f = tid + (i << 8);
            int r = f >> 3, c4 = (f & 7) << 2;
            float4 av = *(const float4*)(A + (size_t)(m0 + r)*K + k0 + c4);
            float4 bv = *(const float4*)(W + (size_t)(n0 + r)*K + k0 + c4);
            As[r][c4+0] = tf32r(av.x); As[r][c4+1] = tf32r(av.y);
            As[r][c4+2] = tf32r(av.z); As[r][c4+3] = tf32r(av.w);
            Bs[r][c4+0] = tf32r(bv.x); Bs[r][c4+1] = tf32r(bv.y);
            Bs[r][c4+2] = tf32r(bv.z); Bs[r][c4+3] = tf32r(bv.w);
        }
        __syncthreads();
        #pragma unroll
        for (int k8 = 0; k8 < 32; k8 += 8) {
            unsigned af[4][4], bf[4][2];
            int kk = k8 + (lane & 3);
            #pragma unroll
            for (int ma = 0; ma < 4; ++ma) {
                int r = (warp_m << 6) + (ma << 4) + (lane >> 2);
                af[ma][0] = __float_as_uint(As[r][kk]);
                af[ma][1] = __float_as_uint(As[r+8][kk]);
                af[ma][2] = __float_as_uint(As[r][kk+4]);
                af[ma][3] = __float_as_uint(As[r+8][kk+4]);
            }
            #pragma unroll
            for (int na = 0; na < 4; ++na) {
                int cn = (warp_n << 5) + (na << 3) + (lane >> 2);
                bf[na][0] = __float_as_uint(Bs[cn][kk]);
                bf[na][1] = __float_as_uint(Bs[cn][kk+4]);
            }
            #pragma unroll
            for (int ma = 0; ma < 4; ++ma)
                #pragma unroll
                for (int na = 0; na < 4; ++na)
                    mma8(acc[ma][na], af[ma], bf[na]);
        }
        __syncthreads();
    }

    #pragma unroll
    for (int ma = 0; ma < 4; ++ma) {
        int r = m0 + (warp_m << 6) + (ma << 4) + (lane >> 2);
        #pragma unroll
        for (int na = 0; na < 4; ++na) {
            int c = n0 + (warp_n << 5) + (na << 3) + ((lane & 3) << 1);
            float b0v = bias[c], b1v = bias[c+1];
            C[(size_t)r*N + c]       = acc[ma][na][0] + b0v;
            C[(size_t)r*N + c + 1]   = acc[ma][na][1] + b1v;
            C[(size_t)(r+8)*N + c]   = acc[ma][na][2] + b0v;
            C[(size_t)(r+8)*N + c+1] = acc[ma][na][3] + b1v;
        }
    }
}

// ------------------------- BiLSTM recurrence (round-12 proven version) -------------------------
__global__ void __launch_bounds__(256) lstm_k(
    const float* __restrict__ xgf, const float* __restrict__ xgb,
    const float* __restrict__ whhfI, const float* __restrict__ whhbI,
    float* __restrict__ out) {
    int tid = threadIdx.x;
    int dir = blockIdx.y;
    int b0  = blockIdx.x << 1;
    const float* xg = dir ? xgb : xgf;
    const float* w  = dir ? whhbI : whhfI;
    __shared__ float hs[2][HID_];
    hs[0][tid] = 0.f; hs[1][tid] = 0.f;
    float c0 = 0.f, c1 = 0.f;
    for (int step = 0; step < S_; ++step) {
        __syncthreads();
        float a00=0.f,a01=0.f,a02=0.f,a03=0.f;
        float a10=0.f,a11=0.f,a12=0.f,a13=0.f;
        const float* wp = w + 4*tid;
        #pragma unroll 16
        for (int k = 0; k < HID_; ++k) {
            float h0v = hs[0][k], h1v = hs[1][k];
            float4 w4 = *(const float4*)(wp + (size_t)k*G4_);
            a00 = fmaf(h0v, w4.x, a00); a10 = fmaf(h1v, w4.x, a10);
            a01 = fmaf(h0v, w4.y, a01); a11 = fmaf(h1v, w4.y, a11);
            a02 = fmaf(h0v, w4.z, a02); a12 = fmaf(h1v, w4.z, a12);
            a03 = fmaf(h0v, w4.w, a03); a13 = fmaf(h1v, w4.w, a13);
        }
        int t = dir ? (S_-1-step) : step;
        const float* x0 = xg + ((size_t)b0    *S_ + t)*G4_;
        const float* x1 = xg + ((size_t)(b0+1)*S_ + t)*G4_;
        a00 += x0[tid]; a01 += x0[tid+256]; a02 += x0[tid+512]; a03 += x0[tid+768];
        a10 += x1[tid]; a11 += x1[tid+256]; a12 += x1[tid+512]; a13 += x1[tid+768];
        c0 = sigm_(a01)*c0 + sigm_(a00)*tanhf(a02);
        float h0n = sigm_(a03)*tanhf(c0);
        c1 = sigm_(a11)*c1 + sigm_(a10)*tanhf(a12);
        float h1n = sigm_(a13)*tanhf(c1);
        __syncthreads();
        hs[0][tid] = h0n; hs[1][tid] = h1n;
        out[((size_t)b0    *S_ + t)*D2_ + dir*HID_ + tid] = h0n;
        out[((size_t)(b0+1)*S_ + t)*D2_ + dir*HID_ + tid] = h1n;
    }
}

// ------------------------- attention scores -------------------------
__global__ void __launch_bounds__(256) attn_scores_k(
    const float* __restrict__ q, const float* __restrict__ k,
    float* __restrict__ attn) {
    __shared__ float Qs[64][65];
    __shared__ float Ks[64][65];
    int tid = threadIdx.x;
    int bh = blockIdx.z; int b = bh >> 3, h = bh & 7;
    int s0 = blockIdx.y << 6, t0 = blockIdx.x << 6;
    const float* qb = q + ((size_t)b*S_ + s0)*D2_ + h*64;
    const float* kb = k + ((size_t)b*S_ + t0)*D2_ + h*64;
    for (int i = tid; i < 64*64; i += 256) {
        int r = i >> 6, cc = i & 63;
        Qs[r][cc] = qb[(size_t)r*D2_ + cc];
        Ks[r][cc] = kb[(size_t)r*D2_ + cc];
    }
    __syncthreads();
    int tr = tid >> 4, tc = tid & 15;
    float acc[4][4];
    #pragma unroll
    for (int i = 0; i < 4; ++i)
        #pragma unroll
        for (int j = 0; j < 4; ++j) acc[i][j] = 0.f;
    #pragma unroll 4
    for (int d = 0; d < 64; ++d) {
        float qa[4], ka[4];
        #pragma unroll
        for (int i = 0; i < 4; ++i) qa[i] = Qs[tr*4+i][d];
        #pragma unroll
        for (int j = 0; j < 4; ++j) ka[j] = Ks[tc*4+j][d];
        #pragma unroll
        for (int i = 0; i < 4; ++i)
            #pragma unroll
            for (int j = 0; j < 4; ++j)
                acc[i][j] = fmaf(qa[i], ka[j], acc[i][j]);
    }
    float* ap = attn + (((size_t)bh*S_ + s0 + tr*4)*S_ + t0 + tc*4);
    #pragma unroll
    for (int i = 0; i < 4; ++i)
        #pragma unroll
        for (int j = 0; j < 4; ++j)
            ap[(size_t)i*S_ + j] = acc[i][j] * 0.125f;
}

// ------------------------- log-softmax over heads (axis=1) -------------------------
__global__ void logsoftmax_h_k(float* __restrict__ attn) {
    size_t idx = (size_t)blockIdx.x*blockDim.x + threadIdx.x;
    size_t total = (size_t)B_*S_*S_;
    if (idx >= total) return;
    int t = idx & (S_-1);
    int s = (idx >> 9) & (S_-1);
    int b = idx >> 18;
    float* p = attn + (((size_t)b*NH_)*S_ + s)*S_ + t;
    const size_t hs = (size_t)S_*S_;
    float v[NH_];
    float m = -1e30f;
    #pragma unroll
    for (int h = 0; h < NH_; ++h) { v[h] = p[h*hs]; m = fmaxf(m, v[h]); }
    float sum = 0.f;
    #pragma unroll
    for (int h = 0; h < NH_; ++h) sum += __expf(v[h] - m);
    float lse = __logf(sum) + m;
    #pragma unroll
    for (int h = 0; h < NH_; ++h) p[h*hs] = v[h] - lse;
}

// ------------------------- ctx = la @ v -------------------------
__global__ void __launch_bounds__(256) attn_ctx_k(
    const float* __restrict__ la, const float* __restrict__ v,
    float* __restrict__ ctx) {
    __shared__ float Ls[64][65];
    __shared__ float Vs[64][65];
    int tid = threadIdx.x;
    int bh = blockIdx.y; int b = bh >> 3, h = bh & 7;
    int s0 = blockIdx.x << 6;
    int tr = tid >> 4, tc = tid & 15;
    float acc[4][4];
    #pragma unroll
    for (int i = 0; i < 4; ++i)
        #pragma unroll
        for (int j = 0; j < 4; ++j) acc[i][j] = 0.f;
    for (int t0 = 0; t0 < S_; t0 += 64) {
        for (int i = tid; i < 64*64; i += 256) {
            int r = i >> 6, cc = i & 63;
            Ls[r][cc] = la[(((size_t)bh*S_) + s0 + r)*S_ + t0 + cc];
            Vs[r][cc] = v[((size_t)b*S_ + t0 + r)*D2_ + h*64 + cc];
        }
        __syncthreads();
        #pragma unroll 4
        for (int kk = 0; kk < 64; ++kk) {
            float a[4], bb[4];
            #pragma unroll
            for (int i = 0; i < 4; ++i) a[i] = Ls[tr*4+i][kk];
            #pragma unroll
            for (int j = 0; j < 4; ++j) bb[j] = Vs[kk][tc*4+j];
            #pragma unroll
            for (int i = 0; i < 4; ++i)
                #pragma unroll
                for (int j = 0; j < 4; ++j)
                    acc[i][j] = fmaf(a[i], bb[j], acc[i][j]);
        }
        __syncthreads();
    }
    #pragma unroll
    for (int i = 0; i < 4; ++i) {
        float* cp = ctx + ((size_t)b*S_ + s0 + tr*4 + i)*D2_ + h*64 + tc*4;
        #pragma unroll
        for (int j = 0; j < 4; ++j) cp[j] = acc[i][j];
    }
}

// ------------------------- residual + layernorm -------------------------
__global__ void __launch_bounds__(256) res_ln_k(
    const float* __restrict__ out1, const float* __restrict__ ctx,
    const float* __restrict__ lng, const float* __restrict__ lnb,
    float* __restrict__ r) {
    size_t row = blockIdx.x;
    int tid = threadIdx.x;
    const float* o = out1 + row*D2_;
    const float* c = ctx  + row*D2_;
    float v0 = o[tid] + c[tid];
    float v1 = o[tid+256] + c[tid+256];
    float mu = blockReduceSum(v0 + v1) * (1.f/D2_);
    float d0 = v0 - mu, d1 = v1 - mu;
    float var = blockReduceSum(d0*d0 + d1*d1) * (1.f/D2_);
    float rs = rsqrtf(var + 1e-5f);
    r[row*D2_ + tid]       = d0*rs*lng[tid]     + lnb[tid];
    r[row*D2_ + tid + 256] = d1*rs*lng[tid+256] + lnb[tid+256];
}

// ------------------------- mean pool + fc -------------------------
__global__ void __launch_bounds__(256) pool_fc_k(
    const float* __restrict__ r, const float* __restrict__ fcw,
    const float* __restrict__ fcb, float* __restrict__ out) {
    int b = blockIdx.x, tid = threadIdx.x;
    const float* rb = r + (size_t)b*S_*D2_;
    float acc = 0.f;
    for (int i = tid; i < S_*D2_; i += 256)
        acc = fmaf(rb[i], fcw[i & (D2_-1)], acc);
    float total = blockReduceSum(acc);
    if (tid == 0) out[b] = total * (1.f/S_) + fcb[0];
}

// ------------------------- launch -------------------------
static float* devptr(const void* sym) {
    void* p = nullptr;
    cudaGetSymbolAddress(&p, sym);
    return (float*)p;
}

extern "C" void kernel_launch(void* const* d_in, const int* in_sizes, int n_in,
                              void* d_out, int out_size) {
    const float* x       = (const float*)d_in[0];
    const float* conv_w  = (const float*)d_in[1];
    const float* conv_b  = (const float*)d_in[2];
    const float* bn_g    = (const float*)d_in[3];
    const float* bn_b    = (const float*)d_in[4];
    const float* bn_m    = (const float*)d_in[5];
    const float* bn_v    = (const float*)d_in[6];
    const float* W_ih0f  = (const float*)d_in[7];
    const float* W_hh0f  = (const float*)d_in[8];
    const float* b0f     = (const float*)d_in[9];
    const float* W_ih0b  = (const float*)d_in[10];
    const float* W_hh0b  = (const float*)d_in[11];
    const float* b0b     = (const float*)d_in[12];
    const float* W_ih1f  = (const float*)d_in[13];
    const float* W_hh1f  = (const float*)d_in[14];
    const float* b1f     = (const float*)d_in[15];
    const float* W_ih1b  = (const float*)d_in[16];
    const float* W_hh1b  = (const float*)d_in[17];
    const float* b1b     = (const float*)d_in[18];
    const float* Wq      = (const float*)d_in[19];
    const float* bq      = (const float*)d_in[20];
    const float* Wk      = (const float*)d_in[21];
    const float* bk      = (const float*)d_in[22];
    const float* Wv      = (const float*)d_in[23];
    const float* bv      = (const float*)d_in[24];
    const float* ln_g    = (const float*)d_in[25];
    const float* ln_b    = (const float*)d_in[26];
    const float* fc_w    = (const float*)d_in[27];
    const float* fc_b    = (const float*)d_in[28];
    float* out = (float*)d_out;

    float* p_h0   = devptr(g_h0);
    float* p_xgf  = devptr(g_xgf);
    float* p_xgb  = devptr(g_xgb);
    float* p_out0 = devptr(g_out0);
    float* p_out1 = devptr(g_out1);
    float* p_q    = devptr(g_q);
    float* p_k    = devptr(g_k);
    float* p_v    = devptr(g_v);
    float* p_attn = devptr(g_attn);
    float* p_ctx  = devptr(g_ctx);
    float* p_r    = devptr(g_r);
    float* p_wcT  = devptr(g_wcT);
    float* p_hh0f = devptr(g_whh0fI);
    float* p_hh0b = devptr(g_whh0bI);
    float* p_hh1f = devptr(g_whh1fI);
    float* p_hh1b = devptr(g_whh1bI);

    const int M = B_*S_;  // 32768

    // 1: all weight reshapes in one launch
    reshape_all_k<<<dim3((HID_*G4_+255)/256, 5), 256>>>(
        conv_w, W_hh0f, W_hh0b, W_hh1f, W_hh1b,
        p_wcT, p_hh0f, p_hh0b, p_hh1f, p_hh1b);

    // 2: conv front-end
    conv_bn_pool_k<<<dim3(S_/4, B_), 128>>>(x, p_wcT, conv_b, bn_g, bn_b, bn_m, bn_v, p_h0);

    // 3-5: layer 0 gates (TF32 TC) + recurrence
    gemm_tf32_k<<<dim3(G4_/128, M/128), 256>>>(p_h0, W_ih0f, b0f, p_xgf, M, G4_, C_);
    gemm_tf32_k<<<dim3(G4_/128, M/128), 256>>>(p_h0, W_ih0b, b0b, p_xgb, M, G4_, C_);
    lstm_k<<<dim3(B_/2, 2), 256>>>(p_xgf, p_xgb, p_hh0f, p_hh0b, p_out0);

    // 6-8: layer 1 gates + recurrence   (launch #6 = ncu sample target)
    gemm_tf32_k<<<dim3(G4_/128, M/128), 256>>>(p_out0, W_ih1f, b1f, p_xgf, M, G4_, D2_);
    gemm_tf32_k<<<dim3(G4_/128, M/128), 256>>>(p_out0, W_ih1b, b1b, p_xgb, M, G4_, D2_);
    lstm_k<<<dim3(B_/2, 2), 256>>>(p_xgf, p_xgb, p_hh1f, p_hh1b, p_out1);

    // 9-11: QKV
    gemm_tf32_k<<<dim3(D2_/128, M/128), 256>>>(p_out1, Wq, bq, p_q, M, D2_, D2_);
    gemm_tf32_k<<<dim3(D2_/128, M/128), 256>>>(p_out1, Wk, bk, p_k, M, D2_, D2_);
    gemm_tf32_k<<<dim3(D2_/128, M/128), 256>>>(p_out1, Wv, bv, p_v, M, D2_, D2_);

    // attention
    attn_scores_k<<<dim3(S_/64, S_/64, B_*NH_), 256>>>(p_q, p_k, p_attn);
    logsoftmax_h_k<<<(int)(((size_t)B_*S_*S_ + 255)/256), 256>>>(p_attn);
    attn_ctx_k<<<dim3(S_/64, B_*NH_), 256>>>(p_attn, p_v, p_ctx);

    // residual + LN + pool + fc
    res_ln_k<<<M, 256>>>(p_out1, p_ctx, ln_g, ln_b, p_r);
    pool_fc_k<<<B_, 256>>>(p_r, fc_w, fc_b, out);

    (void)in_sizes; (void)n_in; (void)out_size;
}

// round 15
// speedup vs baseline: 1.3375x; 1.0468x over previous
#include <cuda_runtime.h>
#include <math.h>

#define B_   64
#define C_   32
#define L_   1549
#define S_   512
#define HID_ 256
#define G4_  1024
#define D2_  512
#define NH_  8

// ------------------------- scratch (device globals) -------------------------
__device__ float g_h0 [(size_t)B_*S_*C_];
__device__ float g_xgf[(size_t)B_*S_*G4_];
__device__ float g_xgb[(size_t)B_*S_*G4_];
__device__ float g_out0[(size_t)B_*S_*D2_];
__device__ float g_out1[(size_t)B_*S_*D2_];
__device__ float g_q[(size_t)B_*S_*D2_];
__device__ float g_k[(size_t)B_*S_*D2_];
__device__ float g_v[(size_t)B_*S_*D2_];
__device__ float g_attn[(size_t)B_*NH_*S_*S_];
__device__ float g_ctx[(size_t)B_*S_*D2_];
__device__ float g_r[(size_t)B_*S_*D2_];

__device__ float g_wcT[C_*16*C_];
__device__ float g_whh0fI[HID_*G4_], g_whh0bI[HID_*G4_];
__device__ float g_whh1fI[HID_*G4_], g_whh1bI[HID_*G4_];

__device__ __forceinline__ float sigm_(float x) { return 1.f/(1.f+__expf(-x)); }

__device__ __forceinline__ float tf32r(float x) {
    unsigned u;
    asm("cvt.rna.tf32.f32 %0,%1;" : "=r"(u) : "f"(x));
    return __uint_as_float(u);
}

__device__ __forceinline__ void mma8(float* c, const unsigned* a, const unsigned* b) {
    asm volatile("mma.sync.aligned.m16n8k8.row.col.f32.tf32.tf32.f32 "
        "{%0,%1,%2,%3},{%4,%5,%6,%7},{%8,%9},{%0,%1,%2,%3};"
        : "+f"(c[0]), "+f"(c[1]), "+f"(c[2]), "+f"(c[3])
        : "r"(a[0]), "r"(a[1]), "r"(a[2]), "r"(a[3]), "r"(b[0]), "r"(b[1]));
}

__device__ __forceinline__ float blockReduceSum(float v) {
    __shared__ float sh[32];
    __syncthreads();
    int lane = threadIdx.x & 31, w = threadIdx.x >> 5;
    #pragma unroll
    for (int o = 16; o; o >>= 1) v += __shfl_down_sync(0xffffffffu, v, o);
    if (!lane) sh[w] = v;
    __syncthreads();
    if (w == 0) {
        int nw = blockDim.x >> 5;
        v = (lane < nw) ? sh[lane] : 0.f;
        #pragma unroll
        for (int o = 16; o; o >>= 1) v += __shfl_down_sync(0xffffffffu, v, o);
        if (!lane) sh[0] = v;
    }
    __syncthreads();
    return sh[0];
}

// ------------------------- fused weight reshapes (one launch) -------------------------
__global__ void reshape_all_k(const float* __restrict__ cw,
                              const float* __restrict__ h0f, const float* __restrict__ h0b,
                              const float* __restrict__ h1f, const float* __restrict__ h1b,
                              float* __restrict__ wcT,
                              float* __restrict__ w0f, float* __restrict__ w0b,
                              float* __restrict__ w1f, float* __restrict__ w1b) {
    int idx = blockIdx.x*blockDim.x + threadIdx.x;
    int which = blockIdx.y;
    if (which == 0) {
        if (idx < C_*16*C_) {
            int o = idx % C_, kk = (idx / C_) % 16, i = idx / (C_*16);
            wcT[idx] = cw[((size_t)o*C_ + i)*16 + kk];
        }
    } else {
        const float* in  = (which==1)?h0f:(which==2)?h0b:(which==3)?h1f:h1b;
        float*       out = (which==1)?w0f:(which==2)?w0b:(which==3)?w1f:w1b;
        if (idx < HID_*G4_) {
            int col = idx % G4_, kk = idx / G4_;
            int j = col >> 2, g = col & 3;
            out[idx] = in[((size_t)g*HID_ + j)*HID_ + kk];
        }
    }
}

// ------------------------- conv1d + bn + relu + maxpool3 -------------------------
__global__ void conv_bn_pool_k(const float* __restrict__ x, const float* __restrict__ wcT,
                               const float* __restrict__ cb, const float* __restrict__ gma,
                               const float* __restrict__ bta, const float* __restrict__ mean,
                               const float* __restrict__ var, float* __restrict__ h0) {
    int c  = threadIdx.x & 31;
    int si = threadIdx.x >> 5;
    int s  = (blockIdx.x << 2) + si;
    int b  = blockIdx.y;
    float scale = gma[c] * rsqrtf(var[c] + 1e-5f);
    float shift = bta[c] - mean[c]*scale;
    float a0 = cb[c], a1 = cb[c], a2 = cb[c];
    const float* xb = x + (size_t)b*C_*L_;
    int l0 = 3*s - 1;
    for (int ci = 0; ci < C_; ++ci) {
        const float* xc = xb + (size_t)ci*L_;
        float xv[18];
        #pragma unroll
        for (int qd = 0; qd < 18; ++qd) {
            int idx = l0 + qd;
            xv[qd] = (idx >= 0 && idx < L_) ? xc[idx] : 0.f;
        }
        const float* w = wcT + (size_t)ci*16*C_ + c;
        #pragma unroll
        for (int kk = 0; kk < 16; ++kk) {
            float wv = w[(size_t)kk*C_];
            a0 = fmaf(xv[kk+0], wv, a0);
            a1 = fmaf(xv[kk+1], wv, a1);
            a2 = fmaf(xv[kk+2], wv, a2);
        }
    }
    a0 = fmaxf(fmaf(a0, scale, shift), 0.f);
    a1 = fmaxf(fmaf(a1, scale, shift), 0.f);
    a2 = fmaxf(fmaf(a2, scale, shift), 0.f);
    h0[((size_t)b*S_ + s)*C_ + c] = fmaxf(a0, fmaxf(a1, a2));
}

// ------------------------- TF32 tensor-core GEMM: C = A(MxK) @ W(N,K)^T + bias ----------
__global__ void __launch_bounds__(256) gemm_tf32_k(
    const float* __restrict__ A, const float* __restrict__ W,
    const float* __restrict__ bias, float* __restrict__ C,
    int M, int N, int K) {
    __shared__ float As[128][36];
    __shared__ float Bs[128][36];
    int tid = threadIdx.x;
    int lane = tid & 31, wid = tid >> 5;
    int warp_m = wid & 1, warp_n = wid >> 1;
    int m0 = blockIdx.y << 7, n0 = blockIdx.x << 7;

    float acc[4][4][4];
    #pragma unroll
    for (int i = 0; i < 4; ++i)
        #pragma unroll
        for (int j = 0; j < 4; ++j)
            #pragma unroll
            for (int p = 0; p < 4; ++p) acc[i][j][p] = 0.f;

    for (int k0 = 0; k0 < K; k0 += 32) {
        #pragma unroll
        for (int i = 0; i < 4; ++i) {
            int f = tid + (i << 8);
            int r = f >> 3, c4 = (f & 7) << 2;
            float4 av = *(const float4*)(A + (size_t)(m0 + r)*K + k0 + c4);
            float4 bv = *(const float4*)(W + (size_t)(n0 + r)*K + k0 + c4);
            As[r][c4+0] = tf32r(av.x); As[r][c4+1] = tf32r(av.y);
            As[r][c4+2] = tf32r(av.z); As[r][c4+3] = tf32r(av.w);
            Bs[r][c4+0] = tf32r(bv.x); Bs[r][c4+1] = tf32r(bv.y);
            Bs[r][c4+2] = tf32r(bv.z); Bs[r][c4+3] = tf32r(bv.w);
        }
        __syncthreads();
        #pragma unroll
        for (int k8 = 0; k8 < 32; k8 += 8) {
            unsigned af[4][4], bf[4][2];
            int kk = k8 + (lane & 3);
            #pragma unroll
            for (int ma = 0; ma < 4; ++ma) {
                int r = (warp_m << 6) + (ma << 4) + (lane >> 2);
                af[ma][0] = __float_as_uint(As[r][kk]);
                af[ma][1] = __float_as_uint(As[r+8][kk]);
                af[ma][2] = __float_as_uint(As[r][kk+4]);
                af[ma][3] = __float_as_uint(As[r+8][kk+4]);
            }
            #pragma unroll
            for (int na = 0; na < 4; ++na) {
                int cn = (warp_n << 5) + (na << 3) + (lane >> 2);
                bf[na][0] = __float_as_uint(Bs[cn][kk]);
                bf[na][1] = __float_as_uint(Bs[cn][kk+4]);
            }
            #pragma unroll
            for (int ma = 0; ma < 4; ++ma)
                #pragma unroll
                for (int na = 0; na < 4; ++na)
                    mma8(acc[ma][na], af[ma], bf[na]);
        }
        __syncthreads();
    }

    #pragma unroll
    for (int ma = 0; ma < 4; ++ma) {
        int r = m0 + (warp_m << 6) + (ma << 4) + (lane >> 2);
        #pragma unroll
        for (int na = 0; na < 4; ++na) {
            int c = n0 + (warp_n << 5) + (na << 3) + ((lane & 3) << 1);
            float b0v = bias[c], b1v = bias[c+1];
            C[(size_t)r*N + c]       = acc[ma][na][0] + b0v;
            C[(size_t)r*N + c + 1]   = acc[ma][na][1] + b1v;
            C[(size_t)(r+8)*N + c]   = acc[ma][na][2] + b0v;
            C[(size_t)(r+8)*N + c+1] = acc[ma][na][3] + b1v;
        }
    }
}

// ------------------------- BiLSTM recurrence (proven) -------------------------
__global__ void __launch_bounds__(256) lstm_k(
    const float* __restrict__ xgf, const float* __restrict__ xgb,
    const float* __restrict__ whhfI, const float* __restrict__ whhbI,
    float* __restrict__ out) {
    int tid = threadIdx.x;
    int dir = blockIdx.y;
    int b0  = blockIdx.x << 1;
    const float* xg = dir ? xgb : xgf;
    const float* w  = dir ? whhbI : whhfI;
    __shared__ float hs[2][HID_];
    hs[0][tid] = 0.f; hs[1][tid] = 0.f;
    float c0 = 0.f, c1 = 0.f;
    for (int step = 0; step < S_; ++step) {
        __syncthreads();
        float a00=0.f,a01=0.f,a02=0.f,a03=0.f;
        float a10=0.f,a11=0.f,a12=0.f,a13=0.f;
        const float* wp = w + 4*tid;
        #pragma unroll 16
        for (int k = 0; k < HID_; ++k) {
            float h0v = hs[0][k], h1v = hs[1][k];
            float4 w4 = *(const float4*)(wp + (size_t)k*G4_);
            a00 = fmaf(h0v, w4.x, a00); a10 = fmaf(h1v, w4.x, a10);
            a01 = fmaf(h0v, w4.y, a01); a11 = fmaf(h1v, w4.y, a11);
            a02 = fmaf(h0v, w4.z, a02); a12 = fmaf(h1v, w4.z, a12);
            a03 = fmaf(h0v, w4.w, a03); a13 = fmaf(h1v, w4.w, a13);
        }
        int t = dir ? (S_-1-step) : step;
        const float* x0 = xg + ((size_t)b0    *S_ + t)*G4_;
        const float* x1 = xg + ((size_t)(b0+1)*S_ + t)*G4_;
        a00 += x0[tid]; a01 += x0[tid+256]; a02 += x0[tid+512]; a03 += x0[tid+768];
        a10 += x1[tid]; a11 += x1[tid+256]; a12 += x1[tid+512]; a13 += x1[tid+768];
        c0 = sigm_(a01)*c0 + sigm_(a00)*tanhf(a02);
        float h0n = sigm_(a03)*tanhf(c0);
        c1 = sigm_(a11)*c1 + sigm_(a10)*tanhf(a12);
        float h1n = sigm_(a13)*tanhf(c1);
        __syncthreads();
        hs[0][tid] = h0n; hs[1][tid] = h1n;
        out[((size_t)b0    *S_ + t)*D2_ + dir*HID_ + tid] = h0n;
        out[((size_t)(b0+1)*S_ + t)*D2_ + dir*HID_ + tid] = h1n;
    }
}

// ------------------------- attention scores (TF32 tensor cores) -------------------------
// grid (t-tiles=8, s-tiles=8, B*NH), block 256 = 8 warps (4 m x 2 n).
// attn[b][h][s][t] = (q . k) / 8
__global__ void __launch_bounds__(256) attn_scores_k(
    const float* __restrict__ q, const float* __restrict__ k,
    float* __restrict__ attn) {
    __shared__ float Qs[64][36];
    __shared__ float Ks[64][36];
    int tid = threadIdx.x;
    int lane = tid & 31, wid = tid >> 5;
    int warp_m = wid & 3, warp_n = wid >> 2;
    int bh = blockIdx.z; int b = bh >> 3, h = bh & 7;
    int s0 = blockIdx.y << 6, t0 = blockIdx.x << 6;
    const float* qb = q + ((size_t)b*S_ + s0)*D2_ + h*64;
    const float* kb = k + ((size_t)b*S_ + t0)*D2_ + h*64;

    float acc[4][4];
    #pragma unroll
    for (int i = 0; i < 4; ++i)
        #pragma unroll
        for (int p = 0; p < 4; ++p) acc[i][p] = 0.f;

    // K split: two halves of 32 along d (smem [64][36] holds 32 k at a time)
    #pragma unroll
    for (int half = 0; half < 2; ++half) {
        #pragma unroll
        for (int i = 0; i < 2; ++i) {
            int f = tid + (i << 8);
            int r = f >> 3, c4 = (f & 7) << 2;
            float4 av = *(const float4*)(qb + (size_t)r*D2_ + half*32 + c4);
            float4 bv = *(const float4*)(kb + (size_t)r*D2_ + half*32 + c4);
            Qs[r][c4+0] = tf32r(av.x); Qs[r][c4+1] = tf32r(av.y);
            Qs[r][c4+2] = tf32r(av.z); Qs[r][c4+3] = tf32r(av.w);
            Ks[r][c4+0] = tf32r(bv.x); Ks[r][c4+1] = tf32r(bv.y);
            Ks[r][c4+2] = tf32r(bv.z); Ks[r][c4+3] = tf32r(bv.w);
        }
        __syncthreads();
        #pragma unroll
        for (int k8 = 0; k8 < 32; k8 += 8) {
            int kk = k8 + (lane & 3);
            unsigned af[4], bf[4][2];
            int r = (warp_m << 4) + (lane >> 2);
            af[0] = __float_as_uint(Qs[r][kk]);
            af[1] = __float_as_uint(Qs[r+8][kk]);
            af[2] = __float_as_uint(Qs[r][kk+4]);
            af[3] = __float_as_uint(Qs[r+8][kk+4]);
            #pragma unroll
            for (int na = 0; na < 4; ++na) {
                int cn = (warp_n << 5) + (na << 3) + (lane >> 2);
                bf[na][0] = __float_as_uint(Ks[cn][kk]);
                bf[na][1] = __float_as_uint(Ks[cn][kk+4]);
            }
            #pragma unroll
            for (int na = 0; na < 4; ++na)
                mma8(acc[na], af, bf[na]);
        }
        __syncthreads();
    }

    #pragma unroll
    for (int na = 0; na < 4; ++na) {
        int row = s0 + (warp_m << 4) + (lane >> 2);
        int col = t0 + (warp_n << 5) + (na << 3) + ((lane & 3) << 1);
        float* ap = attn + ((size_t)bh*S_ + row)*S_ + col;
        ap[0]            = acc[na][0] * 0.125f;
        ap[1]            = acc[na][1] * 0.125f;
        ap[(size_t)8*S_]   = acc[na][2] * 0.125f;
        ap[(size_t)8*S_+1] = acc[na][3] * 0.125f;
    }
}

// ------------------------- log-softmax over heads (axis=1) -------------------------
__global__ void logsoftmax_h_k(float* __restrict__ attn) {
    size_t idx = (size_t)blockIdx.x*blockDim.x + threadIdx.x;
    size_t total = (size_t)B_*S_*S_;
    if (idx >= total) return;
    int t = idx & (S_-1);
    int s = (idx >> 9) & (S_-1);
    int b = idx >> 18;
    float* p = attn + (((size_t)b*NH_)*S_ + s)*S_ + t;
    const size_t hs = (size_t)S_*S_;
    float v[NH_];
    float m = -1e30f;
    #pragma unroll
    for (int h = 0; h < NH_; ++h) { v[h] = p[h*hs]; m = fmaxf(m, v[h]); }
    float sum = 0.f;
    #pragma unroll
    for (int h = 0; h < NH_; ++h) sum += __expf(v[h] - m);
    float lse = __logf(sum) + m;
    #pragma unroll
    for (int h = 0; h < NH_; ++h) p[h*hs] = v[h] - lse;
}

// ------------------------- ctx = la @ v (TF32 TC, la split hi/lo for accuracy) ----------
// grid (s-tiles=8, B*NH), block 256 = 8 warps (4 m x 2 n). ctx [b][s][h*64+d]
__global__ void __launch_bounds__(256) attn_ctx_k(
    const float* __restrict__ la, const float* __restrict__ v,
    float* __restrict__ ctx) {
    __shared__ float Lh[64][36];   // la hi (tf32)
    __shared__ float Ll[64][36];   // la lo residual (tf32)
    __shared__ float Vs[64][36];   // V^T : Vs[d][t]
    int tid = threadIdx.x;
    int lane = tid & 31, wid = tid >> 5;
    int warp_m = wid & 3, warp_n = wid >> 2;
    int bh = blockIdx.y; int b = bh >> 3, h = bh & 7;
    int s0 = blockIdx.x << 6;

    float acc[4][4];
    #pragma unroll
    for (int i = 0; i < 4; ++i)
        #pragma unroll
        for (int p = 0; p < 4; ++p) acc[i][p] = 0.f;

    for (int t0 = 0; t0 < S_; t0 += 32) {
        // load la tile [64 s][32 t] split hi/lo; V tile transposed [64 d][32 t]
        #pragma unroll
        for (int i = 0; i < 2; ++i) {
            int f = tid + (i << 8);
            int r = f >> 3, c4 = (f & 7) << 2;   // r: s-row or t-row, c4: 4 cols
            float4 lv = *(const float4*)(la + (((size_t)bh*S_) + s0 + r)*S_ + t0 + c4);
            float hx, hy, hz, hw;
            hx = tf32r(lv.x); hy = tf32r(lv.y); hz = tf32r(lv.z); hw = tf32r(lv.w);
            Lh[r][c4+0] = hx; Lh[r][c4+1] = hy; Lh[r][c4+2] = hz; Lh[r][c4+3] = hw;
            Ll[r][c4+0] = tf32r(lv.x - hx); Ll[r][c4+1] = tf32r(lv.y - hy);
            Ll[r][c4+2] = tf32r(lv.z - hz); Ll[r][c4+3] = tf32r(lv.w - hw);
        }
        // V transposed: 64x32 elements, 2048 / 256 = 8 scalars per thread
        #pragma unroll
        for (int i = 0; i < 8; ++i) {
            int f = tid + (i << 8);
            int tt = f >> 6, dd = f & 63;     // tt: 0..31 local t, dd: d
            Vs[dd][tt] = tf32r(v[((size_t)b*S_ + t0 + tt)*D2_ + h*64 + dd]);
        }
        __syncthreads();
        #pragma unroll
        for (int k8 = 0; k8 < 32; k8 += 8) {
            int kk = k8 + (lane & 3);
            unsigned ah[4], al[4], bf[4][2];
            int r = (warp_m << 4) + (lane >> 2);
            ah[0] = __float_as_uint(Lh[r][kk]);
            ah[1] = __float_as_uint(Lh[r+8][kk]);
            ah[2] = __float_as_uint(Lh[r][kk+4]);
            ah[3] = __float_as_uint(Lh[r+8][kk+4]);
            al[0] = __float_as_uint(Ll[r][kk]);
            al[1] = __float_as_uint(Ll[r+8][kk]);
            al[2] = __float_as_uint(Ll[r][kk+4]);
            al[3] = __float_as_uint(Ll[r+8][kk+4]);
            #pragma unroll
            for (int na = 0; na < 4; ++na) {
                int cn = (warp_n << 5) + (na << 3) + (lane >> 2);
                bf[na][0] = __float_as_uint(Vs[cn][kk]);
                bf[na][1] = __float_as_uint(Vs[cn][kk+4]);
            }
            #pragma unroll
            for (int na = 0; na < 4; ++na) {
                mma8(acc[na], ah, bf[na]);
                mma8(acc[na], al, bf[na]);
            }
        }
        __syncthreads();
    }

    #pragma unroll
    for (int na = 0; na < 4; ++na) {
        int row = s0 + (warp_m << 4) + (lane >> 2);
        int col = (warp_n << 5) + (na << 3) + ((lane & 3) << 1);
        float* cp = ctx + ((size_t)b*S_ + row)*D2_ + h*64 + col;
        cp[0] = acc[na][0];
        cp[1] = acc[na][1];
        cp[(size_t)8*D2_]   = acc[na][2];
        cp[(size_t)8*D2_+1] = acc[na][3];
    }
}

// ------------------------- residual + layernorm -------------------------
__global__ void __launch_bounds__(256) res_ln_k(
    const float* __restrict__ out1, const float* __restrict__ ctx,
    const float* __restrict__ lng, const float* __restrict__ lnb,
    float* __restrict__ r) {
    size_t row = blockIdx.x;
    int tid = threadIdx.x;
    const float* o = out1 + row*D2_;
    const float* c = ctx  + row*D2_;
    float v0 = o[tid] + c[tid];
    float v1 = o[tid+256] + c[tid+256];
    float mu = blockReduceSum(v0 + v1) * (1.f/D2_);
    float d0 = v0 - mu, d1 = v1 - mu;
    float var = blockReduceSum(d0*d0 + d1*d1) * (1.f/D2_);
    float rs = rsqrtf(var + 1e-5f);
    r[row*D2_ + tid]       = d0*rs*lng[tid]     + lnb[tid];
    r[row*D2_ + tid + 256] = d1*rs*lng[tid+256] + lnb[tid+256];
}

// ------------------------- mean pool + fc -------------------------
__global__ void __launch_bounds__(256) pool_fc_k(
    const float* __restrict__ r, const float* __restrict__ fcw,
    const float* __restrict__ fcb, float* __restrict__ out) {
    int b = blockIdx.x, tid = threadIdx.x;
    const float* rb = r + (size_t)b*S_*D2_;
    float acc = 0.f;
    for (int i = tid; i < S_*D2_; i += 256)
        acc = fmaf(rb[i], fcw[i & (D2_-1)], acc);
    float total = blockReduceSum(acc);
    if (tid == 0) out[b] = total * (1.f/S_) + fcb[0];
}

// ------------------------- launch -------------------------
static float* devptr(const void* sym) {
    void* p = nullptr;
    cudaGetSymbolAddress(&p, sym);
    return (float*)p;
}

extern "C" void kernel_launch(void* const* d_in, const int* in_sizes, int n_in,
                              void* d_out, int out_size) {
    const float* x       = (const float*)d_in[0];
    const float* conv_w  = (const float*)d_in[1];
    const float* conv_b  = (const float*)d_in[2];
    const float* bn_g    = (const float*)d_in[3];
    const float* bn_b    = (const float*)d_in[4];
    const float* bn_m    = (const float*)d_in[5];
    const float* bn_v    = (const float*)d_in[6];
    const float* W_ih0f  = (const float*)d_in[7];
    const float* W_hh0f  = (const float*)d_in[8];
    const float* b0f     = (const float*)d_in[9];
    const float* W_ih0b  = (const float*)d_in[10];
    const float* W_hh0b  = (const float*)d_in[11];
    const float* b0b     = (const float*)d_in[12];
    const float* W_ih1f  = (const float*)d_in[13];
    const float* W_hh1f  = (const float*)d_in[14];
    const float* b1f     = (const float*)d_in[15];
    const float* W_ih1b  = (const float*)d_in[16];
    const float* W_hh1b  = (const float*)d_in[17];
    const float* b1b     = (const float*)d_in[18];
    const float* Wq      = (const float*)d_in[19];
    const float* bq      = (const float*)d_in[20];
    const float* Wk      = (const float*)d_in[21];
    const float* bk      = (const float*)d_in[22];
    const float* Wv      = (const float*)d_in[23];
    const float* bv      = (const float*)d_in[24];
    const float* ln_g    = (const float*)d_in[25];
    const float* ln_b    = (const float*)d_in[26];
    const float* fc_w    = (const float*)d_in[27];
    const float* fc_b    = (const float*)d_in[28];
    float* out = (float*)d_out;

    float* p_h0   = devptr(g_h0);
    float* p_xgf  = devptr(g_xgf);
    float* p_xgb  = devptr(g_xgb);
    float* p_out0 = devptr(g_out0);
    float* p_out1 = devptr(g_out1);
    float* p_q    = devptr(g_q);
    float* p_k    = devptr(g_k);
    float* p_v    = devptr(g_v);
    float* p_attn = devptr(g_attn);
    float* p_ctx  = devptr(g_ctx);
    float* p_r    = devptr(g_r);
    float* p_wcT  = devptr(g_wcT);
    float* p_hh0f = devptr(g_whh0fI);
    float* p_hh0b = devptr(g_whh0bI);
    float* p_hh1f = devptr(g_whh1fI);
    float* p_hh1b = devptr(g_whh1bI);

    const int M = B_*S_;  // 32768

    reshape_all_k<<<dim3((HID_*G4_+255)/256, 5), 256>>>(
        conv_w, W_hh0f, W_hh0b, W_hh1f, W_hh1b,
        p_wcT, p_hh0f, p_hh0b, p_hh1f, p_hh1b);

    conv_bn_pool_k<<<dim3(S_/4, B_), 128>>>(x, p_wcT, conv_b, bn_g, bn_b, bn_m, bn_v, p_h0);

    gemm_tf32_k<<<dim3(G4_/128, M/128), 256>>>(p_h0, W_ih0f, b0f, p_xgf, M, G4_, C_);
    gemm_tf32_k<<<dim3(G4_/128, M/128), 256>>>(p_h0, W_ih0b, b0b, p_xgb, M, G4_, C_);
    lstm_k<<<dim3(B_/2, 2), 256>>>(p_xgf, p_xgb, p_hh0f, p_hh0b, p_out0);

    gemm_tf32_k<<<dim3(G4_/128, M/128), 256>>>(p_out0, W_ih1f, b1f, p_xgf, M, G4_, D2_);
    gemm_tf32_k<<<dim3(G4_/128, M/128), 256>>>(p_out0, W_ih1b, b1b, p_xgb, M, G4_, D2_);
    lstm_k<<<dim3(B_/2, 2), 256>>>(p_xgf, p_xgb, p_hh1f, p_hh1b, p_out1);

    gemm_tf32_k<<<dim3(D2_/128, M/128), 256>>>(p_out1, Wq, bq, p_q, M, D2_, D2_);
    gemm_tf32_k<<<dim3(D2_/128, M/128), 256>>>(p_out1, Wk, bk, p_k, M, D2_, D2_);
    gemm_tf32_k<<<dim3(D2_/128, M/128), 256>>>(p_out1, Wv, bv, p_v, M, D2_, D2_);

    attn_scores_k<<<dim3(S_/64, S_/64, B_*NH_), 256>>>(p_q, p_k, p_attn);
    logsoftmax_h_k<<<(int)(((size_t)B_*S_*S_ + 255)/256), 256>>>(p_attn);
    attn_ctx_k<<<dim3(S_/64, B_*NH_), 256>>>(p_attn, p_v, p_ctx);

    res_ln_k<<<M, 256>>>(p_out1, p_ctx, ln_g, ln_b, p_r);
    pool_fc_k<<<B_, 256>>>(p_r, fc_w, fc_b, out);

    (void)in_sizes; (void)n_in; (void)out_size;
}

// round 17
// speedup vs baseline: 1.5214x; 1.1375x over previous
#include <cuda_runtime.h>
#include <cuda_fp16.h>
#include <math.h>

#define B_   64
#define C_   32
#define L_   1549
#define S_   512
#define HID_ 256
#define G4_  1024
#define D2_  512
#define NH_  8

typedef unsigned long long ull;

// ------------------------- scratch (device globals) -------------------------
__device__ float g_h0 [(size_t)B_*S_*C_];
__device__ float g_xgf[(size_t)B_*S_*G4_];
__device__ float g_xgb[(size_t)B_*S_*G4_];
__device__ float g_out0[(size_t)B_*S_*D2_];
__device__ float g_out1[(size_t)B_*S_*D2_];
__device__ float g_q[(size_t)B_*S_*D2_];
__device__ float g_k[(size_t)B_*S_*D2_];
__device__ float g_v[(size_t)B_*S_*D2_];
__device__ float g_attn[(size_t)B_*NH_*S_*S_];
__device__ float g_ctx[(size_t)B_*S_*D2_];
__device__ float g_r[(size_t)B_*S_*D2_];

__device__ float g_wcT[C_*16*C_];
__device__ __half g_whh0fI[HID_*G4_], g_whh0bI[HID_*G4_];
__device__ __half g_whh1fI[HID_*G4_], g_whh1bI[HID_*G4_];

__device__ __forceinline__ float sigm_(float x) { return 1.f/(1.f+__expf(-x)); }

__device__ __forceinline__ float tf32r(float x) {
    unsigned u;
    asm("cvt.rna.tf32.f32 %0,%1;" : "=r"(u) : "f"(x));
    return __uint_as_float(u);
}

__device__ __forceinline__ void mma8(float* c, const unsigned* a, const unsigned* b) {
    asm volatile("mma.sync.aligned.m16n8k8.row.col.f32.tf32.tf32.f32 "
        "{%0,%1,%2,%3},{%4,%5,%6,%7},{%8,%9},{%0,%1,%2,%3};"
        : "+f"(c[0]), "+f"(c[1]), "+f"(c[2]), "+f"(c[3])
        : "r"(a[0]), "r"(a[1]), "r"(a[2]), "r"(a[3]), "r"(b[0]), "r"(b[1]));
}

__device__ __forceinline__ float blockReduceSum(float v) {
    __shared__ float sh[32];
    __syncthreads();
    int lane = threadIdx.x & 31, w = threadIdx.x >> 5;
    #pragma unroll
    for (int o = 16; o; o >>= 1) v += __shfl_down_sync(0xffffffffu, v, o);
    if (!lane) sh[w] = v;
    __syncthreads();
    if (w == 0) {
        int nw = blockDim.x >> 5;
        v = (lane < nw) ? sh[lane] : 0.f;
        #pragma unroll
        for (int o = 16; o; o >>= 1) v += __shfl_down_sync(0xffffffffu, v, o);
        if (!lane) sh[0] = v;
    }
    __syncthreads();
    return sh[0];
}

// ------------------------- fused weight reshapes (one launch) -------------------------
// y=0: conv_w -> wcT[i][k][o]; y=1..4: W_hh -> fp16 interleaved [k][4j+g]
__global__ void reshape_all_k(const float* __restrict__ cw,
                              const float* __restrict__ h0f, const float* __restrict__ h0b,
                              const float* __restrict__ h1f, const float* __restrict__ h1b,
                              float* __restrict__ wcT,
                              __half* __restrict__ w0f, __half* __restrict__ w0b,
                              __half* __restrict__ w1f, __half* __restrict__ w1b) {
    int idx = blockIdx.x*blockDim.x + threadIdx.x;
    int which = blockIdx.y;
    if (which == 0) {
        if (idx < C_*16*C_) {
            int o = idx % C_, kk = (idx / C_) % 16, i = idx / (C_*16);
            wcT[idx] = cw[((size_t)o*C_ + i)*16 + kk];
        }
    } else {
        const float* in = (which==1)?h0f:(which==2)?h0b:(which==3)?h1f:h1b;
        __half* out = (which==1)?w0f:(which==2)?w0b:(which==3)?w1f:w1b;
        if (idx < HID_*G4_) {
            int col = idx % G4_, kk = idx / G4_;
            int j = col >> 2, g = col & 3;
            out[idx] = __float2half_rn(in[((size_t)g*HID_ + j)*HID_ + kk]);
        }
    }
}

// ------------------------- conv1d + bn + relu + maxpool3 -------------------------
__global__ void conv_bn_pool_k(const float* __restrict__ x, const float* __restrict__ wcT,
                               const float* __restrict__ cb, const float* __restrict__ gma,
                               const float* __restrict__ bta, const float* __restrict__ mean,
                               const float* __restrict__ var, float* __restrict__ h0) {
    int c  = threadIdx.x & 31;
    int si = threadIdx.x >> 5;
    int s  = (blockIdx.x << 2) + si;
    int b  = blockIdx.y;
    float scale = gma[c] * rsqrtf(var[c] + 1e-5f);
    float shift = bta[c] - mean[c]*scale;
    float a0 = cb[c], a1 = cb[c], a2 = cb[c];
    const float* xb = x + (size_t)b*C_*L_;
    int l0 = 3*s - 1;
    for (int ci = 0; ci < C_; ++ci) {
        const float* xc = xb + (size_t)ci*L_;
        float xv[18];
        #pragma unroll
        for (int qd = 0; qd < 18; ++qd) {
            int idx = l0 + qd;
            xv[qd] = (idx >= 0 && idx < L_) ? xc[idx] : 0.f;
        }
        const float* w = wcT + (size_t)ci*16*C_ + c;
        #pragma unroll
        for (int kk = 0; kk < 16; ++kk) {
            float wv = w[(size_t)kk*C_];
            a0 = fmaf(xv[kk+0], wv, a0);
            a1 = fmaf(xv[kk+1], wv, a1);
            a2 = fmaf(xv[kk+2], wv, a2);
        }
    }
    a0 = fmaxf(fmaf(a0, scale, shift), 0.f);
    a1 = fmaxf(fmaf(a1, scale, shift), 0.f);
    a2 = fmaxf(fmaf(a2, scale, shift), 0.f);
    h0[((size_t)b*S_ + s)*C_ + c] = fmaxf(a0, fmaxf(a1, a2));
}

// ------------------------- TF32 TC GEMM, z-multiplexed: C_z = A @ W_z^T + bias_z ----------
__global__ void __launch_bounds__(256) gemm_tf32_z_k(
    const float* __restrict__ A,
    const float* __restrict__ W0, const float* __restrict__ W1, const float* __restrict__ W2,
    const float* __restrict__ bias0, const float* __restrict__ bias1, const float* __restrict__ bias2,
    float* __restrict__ C0, float* __restrict__ C1, float* __restrict__ C2,
    int M, int N, int K) {
    int z = blockIdx.z;
    const float* W    = (z==0)?W0:(z==1)?W1:W2;
    const float* bias = (z==0)?bias0:(z==1)?bias1:bias2;
    float* C          = (z==0)?C0:(z==1)?C1:C2;

    __shared__ float As[128][36];
    __shared__ float Bs[128][36];
    int tid = threadIdx.x;
    int lane = tid & 31, wid = tid >> 5;
    int warp_m = wid & 1, warp_n = wid >> 1;
    int m0 = blockIdx.y << 7, n0 = blockIdx.x << 7;

    float acc[4][4][4];
    #pragma unroll
    for (int i = 0; i < 4; ++i)
        #pragma unroll
        for (int j = 0; j < 4; ++j)
            #pragma unroll
            for (int p = 0; p < 4; ++p) acc[i][j][p] = 0.f;

    for (int k0 = 0; k0 < K; k0 += 32) {
        #pragma unroll
        for (int i = 0; i < 4; ++i) {
            int f = tid + (i << 8);
            int r = f >> 3, c4 = (f & 7) << 2;
            float4 av = *(const float4*)(A + (size_t)(m0 + r)*K + k0 + c4);
            float4 bv = *(const float4*)(W + (size_t)(n0 + r)*K + k0 + c4);
            As[r][c4+0] = tf32r(av.x); As[r][c4+1] = tf32r(av.y);
            As[r][c4+2] = tf32r(av.z); As[r][c4+3] = tf32r(av.w);
            Bs[r][c4+0] = tf32r(bv.x); Bs[r][c4+1] = tf32r(bv.y);
            Bs[r][c4+2] = tf32r(bv.z); Bs[r][c4+3] = tf32r(bv.w);
        }
        __syncthreads();
        #pragma unroll
        for (int k8 = 0; k8 < 32; k8 += 8) {
            unsigned af[4][4], bf[4][2];
            int kk = k8 + (lane & 3);
            #pragma unroll
            for (int ma = 0; ma < 4; ++ma) {
                int r = (warp_m << 6) + (ma << 4) + (lane >> 2);
                af[ma][0] = __float_as_uint(As[r][kk]);
                af[ma][1] = __float_as_uint(As[r+8][kk]);
                af[ma][2] = __float_as_uint(As[r][kk+4]);
                af[ma][3] = __float_as_uint(As[r+8][kk+4]);
            }
            #pragma unroll
            for (int na = 0; na < 4; ++na) {
                int cn = (warp_n << 5) + (na << 3) + (lane >> 2);
                bf[na][0] = __float_as_uint(Bs[cn][kk]);
                bf[na][1] = __float_as_uint(Bs[cn][kk+4]);
            }
            #pragma unroll
            for (int ma = 0; ma < 4; ++ma)
                #pragma unroll
                for (int na = 0; na < 4; ++na)
                    mma8(acc[ma][na], af[ma], bf[na]);
        }
        __syncthreads();
    }

    #pragma unroll
    for (int ma = 0; ma < 4; ++ma) {
        int r = m0 + (warp_m << 6) + (ma << 4) + (lane >> 2);
        #pragma unroll
        for (int na = 0; na < 4; ++na) {
            int c = n0 + (warp_n << 5) + (na << 3) + ((lane & 3) << 1);
            float b0v = bias[c], b1v = bias[c+1];
            C[(size_t)r*N + c]       = acc[ma][na][0] + b0v;
            C[(size_t)r*N + c + 1]   = acc[ma][na][1] + b1v;
            C[(size_t)(r+8)*N + c]   = acc[ma][na][2] + b0v;
            C[(size_t)(r+8)*N + c+1] = acc[ma][na][3] + b1v;
        }
    }
}

// ------------------------- BiLSTM recurrence (fp16 weights) -------------------------
// grid (B/2, 2 dirs), block 256. whhI interleaved fp16: [k][4*j + {i,f,g,o}].
__global__ void __launch_bounds__(256) lstm_k(
    const float* __restrict__ xgf, const float* __restrict__ xgb,
    const __half* __restrict__ whhfI, const __half* __restrict__ whhbI,
    float* __restrict__ out) {
    int tid = threadIdx.x;
    int dir = blockIdx.y;
    int b0  = blockIdx.x << 1;
    const float* xg = dir ? xgb : xgf;
    const __half* w = dir ? whhbI : whhfI;
    __shared__ float hs[2][HID_];
    hs[0][tid] = 0.f; hs[1][tid] = 0.f;
    float c0 = 0.f, c1 = 0.f;
    const __half* wp = w + 4*tid;
    for (int step = 0; step < S_; ++step) {
        __syncthreads();
        float a00=0.f,a01=0.f,a02=0.f,a03=0.f;
        float a10=0.f,a11=0.f,a12=0.f,a13=0.f;
        #pragma unroll 16
        for (int k = 0; k < HID_; ++k) {
            ull raw = *(const ull*)(wp + (size_t)k*G4_);
            float h0v = hs[0][k], h1v = hs[1][k];
            __half2 p0 = ((const __half2*)&raw)[0];
            __half2 p1 = ((const __half2*)&raw)[1];
            float2 f0 = __half22float2(p0);
            float2 f1 = __half22float2(p1);
            a00 = fmaf(h0v, f0.x, a00); a10 = fmaf(h1v, f0.x, a10);
            a01 = fmaf(h0v, f0.y, a01); a11 = fmaf(h1v, f0.y, a11);
            a02 = fmaf(h0v, f1.x, a02); a12 = fmaf(h1v, f1.x, a12);
            a03 = fmaf(h0v, f1.y, a03); a13 = fmaf(h1v, f1.y, a13);
        }
        int t = dir ? (S_-1-step) : step;
        const float* x0 = xg + ((size_t)b0    *S_ + t)*G4_;
        const float* x1 = xg + ((size_t)(b0+1)*S_ + t)*G4_;
        a00 += x0[tid]; a01 += x0[tid+256]; a02 += x0[tid+512]; a03 += x0[tid+768];
        a10 += x1[tid]; a11 += x1[tid+256]; a12 += x1[tid+512]; a13 += x1[tid+768];
        c0 = sigm_(a01)*c0 + sigm_(a00)*tanhf(a02);
        float h0n = sigm_(a03)*tanhf(c0);
        c1 = sigm_(a11)*c1 + sigm_(a10)*tanhf(a12);
        float h1n = sigm_(a13)*tanhf(c1);
        __syncthreads();
        hs[0][tid] = h0n; hs[1][tid] = h1n;
        out[((size_t)b0    *S_ + t)*D2_ + dir*HID_ + tid] = h0n;
        out[((size_t)(b0+1)*S_ + t)*D2_ + dir*HID_ + tid] = h1n;
    }
}

// ------------------------- attention scores (TF32 TC) -------------------------
__global__ void __launch_bounds__(256) attn_scores_k(
    const float* __restrict__ q, const float* __restrict__ k,
    float* __restrict__ attn) {
    __shared__ float Qs[64][36];
    __shared__ float Ks[64][36];
    int tid = threadIdx.x;
    int lane = tid & 31, wid = tid >> 5;
    int warp_m = wid & 3, warp_n = wid >> 2;
    int bh = blockIdx.z; int b = bh >> 3, h = bh & 7;
    int s0 = blockIdx.y << 6, t0 = blockIdx.x << 6;
    const float* qb = q + ((size_t)b*S_ + s0)*D2_ + h*64;
    const float* kb = k + ((size_t)b*S_ + t0)*D2_ + h*64;

    float acc[4][4];
    #pragma unroll
    for (int i = 0; i < 4; ++i)
        #pragma unroll
        for (int p = 0; p < 4; ++p) acc[i][p] = 0.f;

    #pragma unroll
    for (int half = 0; half < 2; ++half) {
        #pragma unroll
        for (int i = 0; i < 2; ++i) {
            int f = tid + (i << 8);
            int r = f >> 3, c4 = (f & 7) << 2;
            float4 av = *(const float4*)(qb + (size_t)r*D2_ + half*32 + c4);
            float4 bv = *(const float4*)(kb + (size_t)r*D2_ + half*32 + c4);
            Qs[r][c4+0] = tf32r(av.x); Qs[r][c4+1] = tf32r(av.y);
            Qs[r][c4+2] = tf32r(av.z); Qs[r][c4+3] = tf32r(av.w);
            Ks[r][c4+0] = tf32r(bv.x); Ks[r][c4+1] = tf32r(bv.y);
            Ks[r][c4+2] = tf32r(bv.z); Ks[r][c4+3] = tf32r(bv.w);
        }
        __syncthreads();
        #pragma unroll
        for (int k8 = 0; k8 < 32; k8 += 8) {
            int kk = k8 + (lane & 3);
            unsigned af[4], bf[4][2];
            int r = (warp_m << 4) + (lane >> 2);
            af[0] = __float_as_uint(Qs[r][kk]);
            af[1] = __float_as_uint(Qs[r+8][kk]);
            af[2] = __float_as_uint(Qs[r][kk+4]);
            af[3] = __float_as_uint(Qs[r+8][kk+4]);
            #pragma unroll
            for (int na = 0; na < 4; ++na) {
                int cn = (warp_n << 5) + (na << 3) + (lane >> 2);
                bf[na][0] = __float_as_uint(Ks[cn][kk]);
                bf[na][1] = __float_as_uint(Ks[cn][kk+4]);
            }
            #pragma unroll
            for (int na = 0; na < 4; ++na)
                mma8(acc[na], af, bf[na]);
        }
        __syncthreads();
    }

    #pragma unroll
    for (int na = 0; na < 4; ++na) {
        int row = s0 + (warp_m << 4) + (lane >> 2);
        int col = t0 + (warp_n << 5) + (na << 3) + ((lane & 3) << 1);
        float* ap = attn + ((size_t)bh*S_ + row)*S_ + col;
        ap[0]              = acc[na][0] * 0.125f;
        ap[1]              = acc[na][1] * 0.125f;
        ap[(size_t)8*S_]   = acc[na][2] * 0.125f;
        ap[(size_t)8*S_+1] = acc[na][3] * 0.125f;
    }
}

// ------------------------- log-softmax over heads (axis=1) -------------------------
__global__ void logsoftmax_h_k(float* __restrict__ attn) {
    size_t idx = (size_t)blockIdx.x*blockDim.x + threadIdx.x;
    size_t total = (size_t)B_*S_*S_;
    if (idx >= total) return;
    int t = idx & (S_-1);
    int s = (idx >> 9) & (S_-1);
    int b = idx >> 18;
    float* p = attn + (((size_t)b*NH_)*S_ + s)*S_ + t;
    const size_t hs = (size_t)S_*S_;
    float v[NH_];
    float m = -1e30f;
    #pragma unroll
    for (int h = 0; h < NH_; ++h) { v[h] = p[h*hs]; m = fmaxf(m, v[h]); }
    float sum = 0.f;
    #pragma unroll
    for (int h = 0; h < NH_; ++h) sum += __expf(v[h] - m);
    float lse = __logf(sum) + m;
    #pragma unroll
    for (int h = 0; h < NH_; ++h) p[h*hs] = v[h] - lse;
}

// ------------------------- ctx = la @ v (TF32 TC, la hi/lo split) ----------
__global__ void __launch_bounds__(256) attn_ctx_k(
    const float* __restrict__ la, const float* __restrict__ v,
    float* __restrict__ ctx) {
    __shared__ float Lh[64][36];
    __shared__ float Ll[64][36];
    __shared__ float Vs[64][36];
    int tid = threadIdx.x;
    int lane = tid & 31, wid = tid >> 5;
    int warp_m = wid & 3, warp_n = wid >> 2;
    int bh = blockIdx.y; int b = bh >> 3, h = bh & 7;
    int s0 = blockIdx.x << 6;

    float acc[4][4];
    #pragma unroll
    for (int i = 0; i < 4; ++i)
        #pragma unroll
        for (int p = 0; p < 4; ++p) acc[i][p] = 0.f;

    for (int t0 = 0; t0 < S_; t0 += 32) {
        #pragma unroll
        for (int i = 0; i < 2; ++i) {
            int f = tid + (i << 8);
            int r = f >> 3, c4 = (f & 7) << 2;
            float4 lv = *(const float4*)(la + (((size_t)bh*S_) + s0 + r)*S_ + t0 + c4);
            float hx = tf32r(lv.x), hy = tf32r(lv.y), hz = tf32r(lv.z), hw = tf32r(lv.w);
            Lh[r][c4+0] = hx; Lh[r][c4+1] = hy; Lh[r][c4+2] = hz; Lh[r][c4+3] = hw;
            Ll[r][c4+0] = tf32r(lv.x - hx); Ll[r][c4+1] = tf32r(lv.y - hy);
            Ll[r][c4+2] = tf32r(lv.z - hz); Ll[r][c4+3] = tf32r(lv.w - hw);
        }
        #pragma unroll
        for (int i = 0; i < 8; ++i) {
            int f = tid + (i << 8);
            int tt = f >> 6, dd = f & 63;
            Vs[dd][tt] = tf32r(v[((size_t)b*S_ + t0 + tt)*D2_ + h*64 + dd]);
        }
        __syncthreads();
        #pragma unroll
        for (int k8 = 0; k8 < 32; k8 += 8) {
            int kk = k8 + (lane & 3);
            unsigned ah[4], al[4], bf[4][2];
            int r = (warp_m << 4) + (lane >> 2);
            ah[0] = __float_as_uint(Lh[r][kk]);
            ah[1] = __float_as_uint(Lh[r+8][kk]);
            ah[2] = __float_as_uint(Lh[r][kk+4]);
            ah[3] = __float_as_uint(Lh[r+8][kk+4]);
            al[0] = __float_as_uint(Ll[r][kk]);
            al[1] = __float_as_uint(Ll[r+8][kk]);
            al[2] = __float_as_uint(Ll[r][kk+4]);
            al[3] = __float_as_uint(Ll[r+8][kk+4]);
            #pragma unroll
            for (int na = 0; na < 4; ++na) {
                int cn = (warp_n << 5) + (na << 3) + (lane >> 2);
                bf[na][0] = __float_as_uint(Vs[cn][kk]);
                bf[na][1] = __float_as_uint(Vs[cn][kk+4]);
            }
            #pragma unroll
            for (int na = 0; na < 4; ++na) {
                mma8(acc[na], ah, bf[na]);
                mma8(acc[na], al, bf[na]);
            }
        }
        __syncthreads();
    }

    #pragma unroll
    for (int na = 0; na < 4; ++na) {
        int row = s0 + (warp_m << 4) + (lane >> 2);
        int col = (warp_n << 5) + (na << 3) + ((lane & 3) << 1);
        float* cp = ctx + ((size_t)b*S_ + row)*D2_ + h*64 + col;
        cp[0] = acc[na][0];
        cp[1] = acc[na][1];
        cp[(size_t)8*D2_]   = acc[na][2];
        cp[(size_t)8*D2_+1] = acc[na][3];
    }
}

// ------------------------- residual + layernorm -------------------------
__global__ void __launch_bounds__(256) res_ln_k(
    const float* __restrict__ out1, const float* __restrict__ ctx,
    const float* __restrict__ lng, const float* __restrict__ lnb,
    float* __restrict__ r) {
    size_t row = blockIdx.x;
    int tid = threadIdx.x;
    const float* o = out1 + row*D2_;
    const float* c = ctx  + row*D2_;
    float v0 = o[tid] + c[tid];
    float v1 = o[tid+256] + c[tid+256];
    float mu = blockReduceSum(v0 + v1) * (1.f/D2_);
    float d0 = v0 - mu, d1 = v1 - mu;
    float var = blockReduceSum(d0*d0 + d1*d1) * (1.f/D2_);
    float rs = rsqrtf(var + 1e-5f);
    r[row*D2_ + tid]       = d0*rs*lng[tid]     + lnb[tid];
    r[row*D2_ + tid + 256] = d1*rs*lng[tid+256] + lnb[tid+256];
}

// ------------------------- mean pool + fc -------------------------
__global__ void __launch_bounds__(256) pool_fc_k(
    const float* __restrict__ r, const float* __restrict__ fcw,
    const float* __restrict__ fcb, float* __restrict__ out) {
    int b = blockIdx.x, tid = threadIdx.x;
    const float* rb = r + (size_t)b*S_*D2_;
    float acc = 0.f;
    for (int i = tid; i < S_*D2_; i += 256)
        acc = fmaf(rb[i], fcw[i & (D2_-1)], acc);
    float total = blockReduceSum(acc);
    if (tid == 0) out[b] = total * (1.f/S_) + fcb[0];
}

// ------------------------- launch -------------------------
static float* devptrf(const void* sym) {
    void* p = nullptr;
    cudaGetSymbolAddress(&p, sym);
    return (float*)p;
}
static __half* devptrh(const void* sym) {
    void* p = nullptr;
    cudaGetSymbolAddress(&p, sym);
    return (__half*)p;
}

extern "C" void kernel_launch(void* const* d_in, const int* in_sizes, int n_in,
                              void* d_out, int out_size) {
    const float* x       = (const float*)d_in[0];
    const float* conv_w  = (const float*)d_in[1];
    const float* conv_b  = (const float*)d_in[2];
    const float* bn_g    = (const float*)d_in[3];
    const float* bn_b    = (const float*)d_in[4];
    const float* bn_m    = (const float*)d_in[5];
    const float* bn_v    = (const float*)d_in[6];
    const float* W_ih0f  = (const float*)d_in[7];
    const float* W_hh0f  = (const float*)d_in[8];
    const float* b0f     = (const float*)d_in[9];
    const float* W_ih0b  = (const float*)d_in[10];
    const float* W_hh0b  = (const float*)d_in[11];
    const float* b0b     = (const float*)d_in[12];
    const float* W_ih1f  = (const float*)d_in[13];
    const float* W_hh1f  = (const float*)d_in[14];
    const float* b1f     = (const float*)d_in[15];
    const float* W_ih1b  = (const float*)d_in[16];
    const float* W_hh1b  = (const float*)d_in[17];
    const float* b1b     = (const float*)d_in[18];
    const float* Wq      = (const float*)d_in[19];
    const float* bq      = (const float*)d_in[20];
    const float* Wk      = (const float*)d_in[21];
    const float* bk      = (const float*)d_in[22];
    const float* Wv      = (const float*)d_in[23];
    const float* bv      = (const float*)d_in[24];
    const float* ln_g    = (const float*)d_in[25];
    const float* ln_b    = (const float*)d_in[26];
    const float* fc_w    = (const float*)d_in[27];
    const float* fc_b    = (const float*)d_in[28];
    float* out = (float*)d_out;

    float* p_h0   = devptrf(g_h0);
    float* p_xgf  = devptrf(g_xgf);
    float* p_xgb  = devptrf(g_xgb);
    float* p_out0 = devptrf(g_out0);
    float* p_out1 = devptrf(g_out1);
    float* p_q    = devptrf(g_q);
    float* p_k    = devptrf(g_k);
    float* p_v    = devptrf(g_v);
    float* p_attn = devptrf(g_attn);
    float* p_ctx  = devptrf(g_ctx);
    float* p_r    = devptrf(g_r);
    float* p_wcT  = devptrf(g_wcT);
    __half* p_hh0f = devptrh(g_whh0fI);
    __half* p_hh0b = devptrh(g_whh0bI);
    __half* p_hh1f = devptrh(g_whh1fI);
    __half* p_hh1b = devptrh(g_whh1bI);

    const int M = B_*S_;  // 32768

    // #1 reshape (all weights, one launch)
    reshape_all_k<<<dim3((HID_*G4_+255)/256, 5), 256>>>(
        conv_w, W_hh0f, W_hh0b, W_hh1f, W_hh1b,
        p_wcT, p_hh0f, p_hh0b, p_hh1f, p_hh1b);

    // #2 conv front-end
    conv_bn_pool_k<<<dim3(S_/4, B_), 128>>>(x, p_wcT, conv_b, bn_g, bn_b, bn_m, bn_v, p_h0);

    // #3 layer-0 gates f+b fused (z=2)
    gemm_tf32_z_k<<<dim3(G4_/128, M/128, 2), 256>>>(
        p_h0, W_ih0f, W_ih0b, W_ih0b, b0f, b0b, b0b, p_xgf, p_xgb, p_xgb, M, G4_, C_);
    // #4 lstm layer 0
    lstm_k<<<dim3(B_/2, 2), 256>>>(p_xgf, p_xgb, p_hh0f, p_hh0b, p_out0);

    // #5 layer-1 gates f+b fused
    gemm_tf32_z_k<<<dim3(G4_/128, M/128, 2), 256>>>(
        p_out0, W_ih1f, W_ih1b, W_ih1b, b1f, b1b, b1b, p_xgf, p_xgb, p_xgb, M, G4_, D2_);
    // #6 lstm layer 1  <-- ncu -s 5 -c 1 capture target
    lstm_k<<<dim3(B_/2, 2), 256>>>(p_xgf, p_xgb, p_hh1f, p_hh1b, p_out1);

    // #7 QKV fused (z=3)
    gemm_tf32_z_k<<<dim3(D2_/128, M/128, 3), 256>>>(
        p_out1, Wq, Wk, Wv, bq, bk, bv, p_q, p_k, p_v, M, D2_, D2_);

    // attention
    attn_scores_k<<<dim3(S_/64, S_/64, B_*NH_), 256>>>(p_q, p_k, p_attn);
    logsoftmax_h_k<<<(int)(((size_t)B_*S_*S_ + 255)/256), 256>>>(p_attn);
    attn_ctx_k<<<dim3(S_/64, B_*NH_), 256>>>(p_attn, p_v, p_ctx);

    // residual + LN + pool + fc
    res_ln_k<<<M, 256>>>(p_out1, p_ctx, ln_g, ln_b, p_r);
    pool_fc_k<<<B_, 256>>>(p_r, fc_w, fc_b, out);

    (void)in_sizes; (void)n_in; (void)out_size;
}